// round 2
// baseline (speedup 1.0000x reference)
#include <cuda_runtime.h>
#include <math.h>

// Problem constants
#define T 1024
#define H 1024
#define F 4096
#define E 8
#define NSLOT (2*T)

// GEMM tiling
#define BM 64
#define BN 64
#define BK 16

// ---------------- device scratch (no allocation allowed) ----------------
__device__ int   g_cnt[E];
__device__ int   g_off[E];
__device__ int   g_fill[E];
__device__ int   g_slot_tok[NSLOT];
__device__ float g_slot_w[NSLOT];
__device__ int   g_tok_slot[NSLOT];   // token t's k-th assignment slot
__device__ int   g_tok_e[NSLOT];
__device__ float g_tok_wt[NSLOT];
__device__ float g_h[(size_t)NSLOT * F];   // 32 MB: gelu(x@w1+b1) per slot
__device__ float g_y[(size_t)NSLOT * H];   // 8 MB: weight*(h@w2+b2) per slot

// ---------------- tiny setup kernels ----------------
__global__ void init_kernel() {
    int i = threadIdx.x;
    if (i < E) { g_cnt[i] = 0; g_fill[i] = 0; }
}

// One warp per token: logits = x[t] . gate_w[e] + gate_b[e]; top-2 + softmax
__global__ void router_kernel(const float* __restrict__ x,
                              const float* __restrict__ gw,
                              const float* __restrict__ gb) {
    int t    = (blockIdx.x * blockDim.x + threadIdx.x) >> 5;
    int lane = threadIdx.x & 31;
    if (t >= T) return;
    const float* xr = x + (size_t)t * H;
    float acc[E];
#pragma unroll
    for (int e = 0; e < E; e++) acc[e] = 0.f;
    for (int h = lane; h < H; h += 32) {
        float xv = xr[h];
#pragma unroll
        for (int e = 0; e < E; e++) acc[e] = fmaf(xv, gw[e * H + h], acc[e]);
    }
#pragma unroll
    for (int e = 0; e < E; e++) {
#pragma unroll
        for (int o = 16; o > 0; o >>= 1)
            acc[e] += __shfl_xor_sync(0xffffffffu, acc[e], o);
    }
    if (lane == 0) {
        float lg[E];
#pragma unroll
        for (int e = 0; e < E; e++) lg[e] = acc[e] + gb[e];
        // top-1 (strict > keeps lowest index on ties, matching top_k)
        int e0 = 0; float l0 = lg[0];
#pragma unroll
        for (int e = 1; e < E; e++) if (lg[e] > l0) { l0 = lg[e]; e0 = e; }
        // top-2
        int e1 = -1; float l1 = -3.0e38f;
#pragma unroll
        for (int e = 0; e < E; e++)
            if (e != e0 && lg[e] > l1) { l1 = lg[e]; e1 = e; }
        // softmax over [l0, l1], l0 >= l1
        float w1v = 1.f / (1.f + expf(l0 - l1));  // weight of second expert
        float w0v = 1.f - w1v;
        g_tok_e [t * 2]     = e0;  g_tok_wt[t * 2]     = w0v;
        g_tok_e [t * 2 + 1] = e1;  g_tok_wt[t * 2 + 1] = w1v;
        atomicAdd(&g_cnt[e0], 1);
        atomicAdd(&g_cnt[e1], 1);
    }
}

__global__ void scan_kernel() {
    if (threadIdx.x == 0) {
        int s = 0;
        for (int e = 0; e < E; e++) { g_off[e] = s; s += g_cnt[e]; }
    }
}

__global__ void place_kernel() {
    int t = blockIdx.x * blockDim.x + threadIdx.x;
    if (t >= T) return;
#pragma unroll
    for (int k = 0; k < 2; k++) {
        int e = g_tok_e[t * 2 + k];
        int local = atomicAdd(&g_fill[e], 1);
        int slot = g_off[e] + local;
        g_slot_tok[slot]    = t;
        g_slot_w[slot]      = g_tok_wt[t * 2 + k];
        g_tok_slot[t * 2 + k] = slot;
    }
}

// ---------------- GEMM1: h = gelu(gather(x) @ w1[e] + b1[e]) ----------------
__global__ __launch_bounds__(256) void gemm1_kernel(
    const float* __restrict__ x, const float* __restrict__ w1,
    const float* __restrict__ b1) {
    int e   = blockIdx.z;
    int cnt = g_cnt[e];
    int m0  = blockIdx.y * BM;
    if (m0 >= cnt) return;            // uniform per block: safe before syncs
    int off = g_off[e];
    int n0  = blockIdx.x * BN;

    __shared__ float As[BK][BM + 4];  // A transposed in smem
    __shared__ float Bs[BK][BN];
    __shared__ int   stok[BM];

    int tid = threadIdx.x;
    if (tid < BM) {
        int r = m0 + tid;
        stok[tid] = (r < cnt) ? g_slot_tok[off + r] : -1;
    }
    __syncthreads();

    int tx = tid & 15, ty = tid >> 4;
    float acc[4][4];
#pragma unroll
    for (int i = 0; i < 4; i++)
#pragma unroll
        for (int j = 0; j < 4; j++) acc[i][j] = 0.f;

    int lr = tid >> 2;                // row within tile (0..63)
    int lk = (tid & 3) * 4;           // k offset (0,4,8,12)
    int atok = stok[lr];
    int bk = tid >> 4;                // 0..15
    int bn = (tid & 15) * 4;          // 0..60
    const float* w1e = w1 + (size_t)e * H * F;

    for (int k0 = 0; k0 < H; k0 += BK) {
        float4 av = make_float4(0.f, 0.f, 0.f, 0.f);
        if (atok >= 0)
            av = *(const float4*)(x + (size_t)atok * H + k0 + lk);
        As[lk + 0][lr] = av.x; As[lk + 1][lr] = av.y;
        As[lk + 2][lr] = av.z; As[lk + 3][lr] = av.w;
        float4 bv = *(const float4*)(w1e + (size_t)(k0 + bk) * F + n0 + bn);
        *(float4*)&Bs[bk][bn] = bv;
        __syncthreads();
#pragma unroll
        for (int k = 0; k < BK; k++) {
            float4 a = *(const float4*)&As[k][ty * 4];
            float4 b = *(const float4*)&Bs[k][tx * 4];
            float ar[4] = {a.x, a.y, a.z, a.w};
            float br[4] = {b.x, b.y, b.z, b.w};
#pragma unroll
            for (int i = 0; i < 4; i++)
#pragma unroll
                for (int j = 0; j < 4; j++)
                    acc[i][j] = fmaf(ar[i], br[j], acc[i][j]);
        }
        __syncthreads();
    }

    const float* b1e = b1 + (size_t)e * F;
    int r0 = ty * 4, c0 = tx * 4;
#pragma unroll
    for (int i = 0; i < 4; i++) {
        int r = m0 + r0 + i;
        if (r >= cnt) break;
        float* hrow = g_h + (size_t)(off + r) * F + n0 + c0;
#pragma unroll
        for (int j = 0; j < 4; j++) {
            float v = acc[i][j] + b1e[n0 + c0 + j];
            hrow[j] = 0.5f * v * (1.f + erff(v * 0.70710678118654752440f));
        }
    }
}

// ---------------- GEMM2: y = weight * (h @ w2[e] + b2[e]) ----------------
__global__ __launch_bounds__(256) void gemm2_kernel(
    const float* __restrict__ w2, const float* __restrict__ b2) {
    int e   = blockIdx.z;
    int cnt = g_cnt[e];
    int m0  = blockIdx.y * BM;
    if (m0 >= cnt) return;
    int off = g_off[e];
    int n0  = blockIdx.x * BN;

    __shared__ float As[BK][BM + 4];
    __shared__ float Bs[BK][BN];

    int tid = threadIdx.x;
    int tx = tid & 15, ty = tid >> 4;
    float acc[4][4];
#pragma unroll
    for (int i = 0; i < 4; i++)
#pragma unroll
        for (int j = 0; j < 4; j++) acc[i][j] = 0.f;

    int lr = tid >> 2;
    int lk = (tid & 3) * 4;
    int arow = m0 + lr;
    const float* Aptr = g_h + (size_t)(off + ((arow < cnt) ? arow : 0)) * F;
    bool avalid = (arow < cnt);
    int bk = tid >> 4;
    int bn = (tid & 15) * 4;
    const float* w2e = w2 + (size_t)e * F * H;

    for (int k0 = 0; k0 < F; k0 += BK) {
        float4 av = make_float4(0.f, 0.f, 0.f, 0.f);
        if (avalid) av = *(const float4*)(Aptr + k0 + lk);
        As[lk + 0][lr] = av.x; As[lk + 1][lr] = av.y;
        As[lk + 2][lr] = av.z; As[lk + 3][lr] = av.w;
        float4 bv = *(const float4*)(w2e + (size_t)(k0 + bk) * H + n0 + bn);
        *(float4*)&Bs[bk][bn] = bv;
        __syncthreads();
#pragma unroll
        for (int k = 0; k < BK; k++) {
            float4 a = *(const float4*)&As[k][ty * 4];
            float4 b = *(const float4*)&Bs[k][tx * 4];
            float ar[4] = {a.x, a.y, a.z, a.w};
            float br[4] = {b.x, b.y, b.z, b.w};
#pragma unroll
            for (int i = 0; i < 4; i++)
#pragma unroll
                for (int j = 0; j < 4; j++)
                    acc[i][j] = fmaf(ar[i], br[j], acc[i][j]);
        }
        __syncthreads();
    }

    const float* b2e = b2 + (size_t)e * H;
    int r0 = ty * 4, c0 = tx * 4;
#pragma unroll
    for (int i = 0; i < 4; i++) {
        int r = m0 + r0 + i;
        if (r >= cnt) break;
        int slot = off + r;
        float wgt = g_slot_w[slot];
        float* yrow = g_y + (size_t)slot * H + n0 + c0;
#pragma unroll
        for (int j = 0; j < 4; j++)
            yrow[j] = wgt * (acc[i][j] + b2e[n0 + c0 + j]);
    }
}

// ---------------- combine: out[t] = y[slot0(t)] + y[slot1(t)] ----------------
__global__ void combine_kernel(float* __restrict__ out) {
    int idx = blockIdx.x * blockDim.x + threadIdx.x;
    int t = idx >> 10;       // / H
    int h = idx & (H - 1);
    int sA = g_tok_slot[t * 2];
    int sB = g_tok_slot[t * 2 + 1];
    out[idx] = g_y[(size_t)sA * H + h] + g_y[(size_t)sB * H + h];
}

// ---------------- launch ----------------
extern "C" void kernel_launch(void* const* d_in, const int* in_sizes, int n_in,
                              void* d_out, int out_size) {
    const float* x  = (const float*)d_in[0];
    const float* gw = (const float*)d_in[1];
    const float* gb = (const float*)d_in[2];
    const float* w1 = (const float*)d_in[3];
    const float* b1 = (const float*)d_in[4];
    const float* w2 = (const float*)d_in[5];
    const float* b2 = (const float*)d_in[6];
    float* out = (float*)d_out;

    init_kernel<<<1, 32>>>();
    router_kernel<<<T / 8, 256>>>(x, gw, gb);
    scan_kernel<<<1, 32>>>();
    place_kernel<<<T / 256, 256>>>();

    dim3 g1(F / BN, T / BM, E);   // (64, 16, 8), blocks beyond count exit early
    gemm1_kernel<<<g1, 256>>>(x, w1, b1);
    dim3 g2(H / BN, T / BM, E);   // (16, 16, 8)
    gemm2_kernel<<<g2, 256>>>(w2, b2);

    combine_kernel<<<(T * H) / 256, 256>>>(out);
}

// round 4
// speedup vs baseline: 1.8227x; 1.8227x over previous
#include <cuda_runtime.h>
#include <math.h>

// Problem constants
#define T 1024
#define H 1024
#define F 4096
#define E 8
#define NSLOT (2*T)

// GEMM tiling (tensor-core version)
#define BM 128
#define BN 64
#define BK 16
#define AS_STRIDE (BM + 4)   // 132: 2-way max bank conflicts on frag loads
#define BS_STRIDE (BN + 4)   // 68

// ---------------- device scratch (no allocation allowed) ----------------
__device__ int   g_cnt[E];
__device__ int   g_off[E];
__device__ int   g_fill[E];
__device__ int   g_slot_tok[NSLOT];
__device__ float g_slot_w[NSLOT];
__device__ int   g_tok_slot[NSLOT];
__device__ int   g_tok_e[NSLOT];
__device__ float g_tok_wt[NSLOT];
__device__ float g_h[(size_t)NSLOT * F];   // 32 MB
__device__ float g_y[(size_t)NSLOT * H];   // 8 MB

// ---------------- helpers ----------------
__device__ __forceinline__ unsigned f2tf32(float f) {
    unsigned r;
    asm("cvt.rna.tf32.f32 %0, %1;" : "=r"(r) : "f"(f));
    return r;
}

__device__ __forceinline__ void mma_tf32(float* c, const unsigned* a, const unsigned* b) {
    asm volatile(
        "mma.sync.aligned.m16n8k8.row.col.f32.tf32.tf32.f32 "
        "{%0,%1,%2,%3}, {%4,%5,%6,%7}, {%8,%9}, {%0,%1,%2,%3};\n"
        : "+f"(c[0]), "+f"(c[1]), "+f"(c[2]), "+f"(c[3])
        : "r"(a[0]), "r"(a[1]), "r"(a[2]), "r"(a[3]), "r"(b[0]), "r"(b[1]));
}

// ---------------- tiny setup kernels ----------------
__global__ void init_kernel() {
    int i = threadIdx.x;
    if (i < E) { g_cnt[i] = 0; g_fill[i] = 0; }
}

__global__ void router_kernel(const float* __restrict__ x,
                              const float* __restrict__ gw,
                              const float* __restrict__ gb) {
    int t    = (blockIdx.x * blockDim.x + threadIdx.x) >> 5;
    int lane = threadIdx.x & 31;
    if (t >= T) return;
    const float* xr = x + (size_t)t * H;
    float acc[E];
#pragma unroll
    for (int e = 0; e < E; e++) acc[e] = 0.f;
    for (int h = lane; h < H; h += 32) {
        float xv = xr[h];
#pragma unroll
        for (int e = 0; e < E; e++) acc[e] = fmaf(xv, gw[e * H + h], acc[e]);
    }
#pragma unroll
    for (int e = 0; e < E; e++) {
#pragma unroll
        for (int o = 16; o > 0; o >>= 1)
            acc[e] += __shfl_xor_sync(0xffffffffu, acc[e], o);
    }
    if (lane == 0) {
        float lg[E];
#pragma unroll
        for (int e = 0; e < E; e++) lg[e] = acc[e] + gb[e];
        int e0 = 0; float l0 = lg[0];
#pragma unroll
        for (int e = 1; e < E; e++) if (lg[e] > l0) { l0 = lg[e]; e0 = e; }
        int e1 = -1; float l1 = -3.0e38f;
#pragma unroll
        for (int e = 0; e < E; e++)
            if (e != e0 && lg[e] > l1) { l1 = lg[e]; e1 = e; }
        float w1v = 1.f / (1.f + expf(l0 - l1));
        float w0v = 1.f - w1v;
        g_tok_e [t * 2]     = e0;  g_tok_wt[t * 2]     = w0v;
        g_tok_e [t * 2 + 1] = e1;  g_tok_wt[t * 2 + 1] = w1v;
        atomicAdd(&g_cnt[e0], 1);
        atomicAdd(&g_cnt[e1], 1);
    }
}

__global__ void scan_kernel() {
    if (threadIdx.x == 0) {
        int s = 0;
        for (int e = 0; e < E; e++) { g_off[e] = s; s += g_cnt[e]; }
    }
}

__global__ void place_kernel() {
    int t = blockIdx.x * blockDim.x + threadIdx.x;
    if (t >= T) return;
#pragma unroll
    for (int k = 0; k < 2; k++) {
        int e = g_tok_e[t * 2 + k];
        int local = atomicAdd(&g_fill[e], 1);
        int slot = g_off[e] + local;
        g_slot_tok[slot]      = t;
        g_slot_w[slot]        = g_tok_wt[t * 2 + k];
        g_tok_slot[t * 2 + k] = slot;
    }
}

// ---------------- GEMM1: h = gelu(gather(x) @ w1[e] + b1[e]) ----------------
// 256 threads = 8 warps, 4x2 warp grid, warp tile 32x32 (2x4 m16n8k8 atoms)
__global__ __launch_bounds__(256) void gemm1_kernel(
    const float* __restrict__ x, const float* __restrict__ w1,
    const float* __restrict__ b1) {
    int e   = blockIdx.z;
    int cnt = g_cnt[e];
    int m0  = blockIdx.y * BM;
    if (m0 >= cnt) return;
    int off = g_off[e];
    int n0  = blockIdx.x * BN;

    __shared__ float As[2][BK][AS_STRIDE];
    __shared__ float Bs[2][BK][BS_STRIDE];
    __shared__ int   stok[BM];

    int tid = threadIdx.x;
    if (tid < BM) {
        int r = m0 + tid;
        stok[tid] = (r < cnt) ? g_slot_tok[off + r] : -1;
    }
    __syncthreads();

    int warp  = tid >> 5;
    int lane  = tid & 31;
    int warpM = warp >> 1;        // 0..3
    int warpN = warp & 1;         // 0..1
    int wm0   = warpM * 32;
    int wn0   = warpN * 32;
    int qid   = lane >> 2;        // 0..7
    int qr    = lane & 3;         // 0..3

    // global-load assignments
    int arow0 = tid >> 1;                 // A: 2 float4 per thread? -> use id scheme
    (void)arow0;
    const float* w1e = w1 + (size_t)e * H * F;

    float acc[2][4][4];
#pragma unroll
    for (int mi = 0; mi < 2; mi++)
#pragma unroll
        for (int nj = 0; nj < 4; nj++)
#pragma unroll
            for (int c = 0; c < 4; c++) acc[mi][nj][c] = 0.f;

    float4 ra[2], rb;
    // A load ids: id = tid + i*256; row = id>>2 (0..127), c4 = id&3 (k chunk)
    int a_row[2], a_c4[2];
#pragma unroll
    for (int i = 0; i < 2; i++) { int id = tid + i * 256; a_row[i] = id >> 2; a_c4[i] = id & 3; }
    int b_k  = tid >> 4;          // 0..15
    int b_c4 = tid & 15;          // 0..15

    // prologue: tile 0
#pragma unroll
    for (int i = 0; i < 2; i++) {
        int tok = stok[a_row[i]];
        ra[i] = (tok >= 0) ? *(const float4*)(x + (size_t)tok * H + a_c4[i] * 4)
                           : make_float4(0.f, 0.f, 0.f, 0.f);
    }
    rb = *(const float4*)(w1e + (size_t)b_k * F + n0 + b_c4 * 4);
#pragma unroll
    for (int i = 0; i < 2; i++) {
        int k = a_c4[i] * 4, r = a_row[i];
        As[0][k + 0][r] = __uint_as_float(f2tf32(ra[i].x));
        As[0][k + 1][r] = __uint_as_float(f2tf32(ra[i].y));
        As[0][k + 2][r] = __uint_as_float(f2tf32(ra[i].z));
        As[0][k + 3][r] = __uint_as_float(f2tf32(ra[i].w));
    }
    {
        int c = b_c4 * 4;
        Bs[0][b_k][c + 0] = __uint_as_float(f2tf32(rb.x));
        Bs[0][b_k][c + 1] = __uint_as_float(f2tf32(rb.y));
        Bs[0][b_k][c + 2] = __uint_as_float(f2tf32(rb.z));
        Bs[0][b_k][c + 3] = __uint_as_float(f2tf32(rb.w));
    }
    __syncthreads();

    const int NK = H / BK;   // 64
    for (int it = 0; it < NK; ++it) {
        int buf = it & 1;
        if (it + 1 < NK) {
            int k0 = (it + 1) * BK;
#pragma unroll
            for (int i = 0; i < 2; i++) {
                int tok = stok[a_row[i]];
                ra[i] = (tok >= 0) ? *(const float4*)(x + (size_t)tok * H + k0 + a_c4[i] * 4)
                                   : make_float4(0.f, 0.f, 0.f, 0.f);
            }
            rb = *(const float4*)(w1e + (size_t)(k0 + b_k) * F + n0 + b_c4 * 4);
        }
        // compute from smem buf
#pragma unroll
        for (int ks = 0; ks < 2; ++ks) {
            unsigned af[2][4], bf[4][2];
            int kb = ks * 8 + qr;
#pragma unroll
            for (int mi = 0; mi < 2; mi++) {
                int r = wm0 + mi * 16 + qid;
                af[mi][0] = __float_as_uint(As[buf][kb][r]);
                af[mi][1] = __float_as_uint(As[buf][kb][r + 8]);
                af[mi][2] = __float_as_uint(As[buf][kb + 4][r]);
                af[mi][3] = __float_as_uint(As[buf][kb + 4][r + 8]);
            }
#pragma unroll
            for (int nj = 0; nj < 4; nj++) {
                int c = wn0 + nj * 8 + qid;
                bf[nj][0] = __float_as_uint(Bs[buf][kb][c]);
                bf[nj][1] = __float_as_uint(Bs[buf][kb + 4][c]);
            }
#pragma unroll
            for (int mi = 0; mi < 2; mi++)
#pragma unroll
                for (int nj = 0; nj < 4; nj++)
                    mma_tf32(acc[mi][nj], af[mi], bf[nj]);
        }
        __syncthreads();
        if (it + 1 < NK) {
            int nb = buf ^ 1;
#pragma unroll
            for (int i = 0; i < 2; i++) {
                int k = a_c4[i] * 4, r = a_row[i];
                As[nb][k + 0][r] = __uint_as_float(f2tf32(ra[i].x));
                As[nb][k + 1][r] = __uint_as_float(f2tf32(ra[i].y));
                As[nb][k + 2][r] = __uint_as_float(f2tf32(ra[i].z));
                As[nb][k + 3][r] = __uint_as_float(f2tf32(ra[i].w));
            }
            int c = b_c4 * 4;
            Bs[nb][b_k][c + 0] = __uint_as_float(f2tf32(rb.x));
            Bs[nb][b_k][c + 1] = __uint_as_float(f2tf32(rb.y));
            Bs[nb][b_k][c + 2] = __uint_as_float(f2tf32(rb.z));
            Bs[nb][b_k][c + 3] = __uint_as_float(f2tf32(rb.w));
            __syncthreads();
        }
    }

    // epilogue: bias + exact gelu, scatter to g_h
    const float* b1e = b1 + (size_t)e * F;
#pragma unroll
    for (int mi = 0; mi < 2; mi++) {
#pragma unroll
        for (int half = 0; half < 2; half++) {
            int r = m0 + wm0 + mi * 16 + qid + half * 8;
            if (r >= cnt) continue;
            float* hrow = g_h + (size_t)(off + r) * F;
#pragma unroll
            for (int nj = 0; nj < 4; nj++) {
                int col = n0 + wn0 + nj * 8 + 2 * qr;
                float v0 = acc[mi][nj][half * 2 + 0] + b1e[col];
                float v1 = acc[mi][nj][half * 2 + 1] + b1e[col + 1];
                hrow[col]     = 0.5f * v0 * (1.f + erff(v0 * 0.70710678118654752440f));
                hrow[col + 1] = 0.5f * v1 * (1.f + erff(v1 * 0.70710678118654752440f));
            }
        }
    }
}

// ---------------- GEMM2: y = weight * (h @ w2[e] + b2[e]) ----------------
__global__ __launch_bounds__(256) void gemm2_kernel(
    const float* __restrict__ w2, const float* __restrict__ b2) {
    int e   = blockIdx.z;
    int cnt = g_cnt[e];
    int m0  = blockIdx.y * BM;
    if (m0 >= cnt) return;
    int off = g_off[e];
    int n0  = blockIdx.x * BN;

    __shared__ float As[2][BK][AS_STRIDE];
    __shared__ float Bs[2][BK][BS_STRIDE];

    int tid = threadIdx.x;
    int warp  = tid >> 5;
    int lane  = tid & 31;
    int warpM = warp >> 1;
    int warpN = warp & 1;
    int wm0   = warpM * 32;
    int wn0   = warpN * 32;
    int qid   = lane >> 2;
    int qr    = lane & 3;

    const float* w2e = w2 + (size_t)e * F * H;

    float acc[2][4][4];
#pragma unroll
    for (int mi = 0; mi < 2; mi++)
#pragma unroll
        for (int nj = 0; nj < 4; nj++)
#pragma unroll
            for (int c = 0; c < 4; c++) acc[mi][nj][c] = 0.f;

    float4 ra[2], rb;
    int a_row[2], a_c4[2];
    bool a_ok[2];
    const float* a_base[2];
#pragma unroll
    for (int i = 0; i < 2; i++) {
        int id = tid + i * 256;
        a_row[i] = id >> 2; a_c4[i] = id & 3;
        int r = m0 + a_row[i];
        a_ok[i] = (r < cnt);
        a_base[i] = g_h + (size_t)(off + (a_ok[i] ? r : 0)) * F;
    }
    int b_k  = tid >> 4;
    int b_c4 = tid & 15;

#pragma unroll
    for (int i = 0; i < 2; i++)
        ra[i] = a_ok[i] ? *(const float4*)(a_base[i] + a_c4[i] * 4)
                        : make_float4(0.f, 0.f, 0.f, 0.f);
    rb = *(const float4*)(w2e + (size_t)b_k * H + n0 + b_c4 * 4);
#pragma unroll
    for (int i = 0; i < 2; i++) {
        int k = a_c4[i] * 4, r = a_row[i];
        As[0][k + 0][r] = __uint_as_float(f2tf32(ra[i].x));
        As[0][k + 1][r] = __uint_as_float(f2tf32(ra[i].y));
        As[0][k + 2][r] = __uint_as_float(f2tf32(ra[i].z));
        As[0][k + 3][r] = __uint_as_float(f2tf32(ra[i].w));
    }
    {
        int c = b_c4 * 4;
        Bs[0][b_k][c + 0] = __uint_as_float(f2tf32(rb.x));
        Bs[0][b_k][c + 1] = __uint_as_float(f2tf32(rb.y));
        Bs[0][b_k][c + 2] = __uint_as_float(f2tf32(rb.z));
        Bs[0][b_k][c + 3] = __uint_as_float(f2tf32(rb.w));
    }
    __syncthreads();

    const int NK = F / BK;   // 256
    for (int it = 0; it < NK; ++it) {
        int buf = it & 1;
        if (it + 1 < NK) {
            int k0 = (it + 1) * BK;
#pragma unroll
            for (int i = 0; i < 2; i++)
                ra[i] = a_ok[i] ? *(const float4*)(a_base[i] + k0 + a_c4[i] * 4)
                                : make_float4(0.f, 0.f, 0.f, 0.f);
            rb = *(const float4*)(w2e + (size_t)(k0 + b_k) * H + n0 + b_c4 * 4);
        }
#pragma unroll
        for (int ks = 0; ks < 2; ++ks) {
            unsigned af[2][4], bf[4][2];
            int kb = ks * 8 + qr;
#pragma unroll
            for (int mi = 0; mi < 2; mi++) {
                int r = wm0 + mi * 16 + qid;
                af[mi][0] = __float_as_uint(As[buf][kb][r]);
                af[mi][1] = __float_as_uint(As[buf][kb][r + 8]);
                af[mi][2] = __float_as_uint(As[buf][kb + 4][r]);
                af[mi][3] = __float_as_uint(As[buf][kb + 4][r + 8]);
            }
#pragma unroll
            for (int nj = 0; nj < 4; nj++) {
                int c = wn0 + nj * 8 + qid;
                bf[nj][0] = __float_as_uint(Bs[buf][kb][c]);
                bf[nj][1] = __float_as_uint(Bs[buf][kb + 4][c]);
            }
#pragma unroll
            for (int mi = 0; mi < 2; mi++)
#pragma unroll
                for (int nj = 0; nj < 4; nj++)
                    mma_tf32(acc[mi][nj], af[mi], bf[nj]);
        }
        __syncthreads();
        if (it + 1 < NK) {
            int nb = buf ^ 1;
#pragma unroll
            for (int i = 0; i < 2; i++) {
                int k = a_c4[i] * 4, r = a_row[i];
                As[nb][k + 0][r] = __uint_as_float(f2tf32(ra[i].x));
                As[nb][k + 1][r] = __uint_as_float(f2tf32(ra[i].y));
                As[nb][k + 2][r] = __uint_as_float(f2tf32(ra[i].z));
                As[nb][k + 3][r] = __uint_as_float(f2tf32(ra[i].w));
            }
            int c = b_c4 * 4;
            Bs[nb][b_k][c + 0] = __uint_as_float(f2tf32(rb.x));
            Bs[nb][b_k][c + 1] = __uint_as_float(f2tf32(rb.y));
            Bs[nb][b_k][c + 2] = __uint_as_float(f2tf32(rb.z));
            Bs[nb][b_k][c + 3] = __uint_as_float(f2tf32(rb.w));
            __syncthreads();
        }
    }

    const float* b2e = b2 + (size_t)e * H;
#pragma unroll
    for (int mi = 0; mi < 2; mi++) {
#pragma unroll
        for (int half = 0; half < 2; half++) {
            int r = m0 + wm0 + mi * 16 + qid + half * 8;
            if (r >= cnt) continue;
            int slot = off + r;
            float wgt = g_slot_w[slot];
            float* yrow = g_y + (size_t)slot * H;
#pragma unroll
            for (int nj = 0; nj < 4; nj++) {
                int col = n0 + wn0 + nj * 8 + 2 * qr;
                yrow[col]     = wgt * (acc[mi][nj][half * 2 + 0] + b2e[col]);
                yrow[col + 1] = wgt * (acc[mi][nj][half * 2 + 1] + b2e[col + 1]);
            }
        }
    }
}

// ---------------- combine ----------------
__global__ void combine_kernel(float* __restrict__ out) {
    int idx = blockIdx.x * blockDim.x + threadIdx.x;
    int t = idx >> 10;
    int h = idx & (H - 1);
    int sA = g_tok_slot[t * 2];
    int sB = g_tok_slot[t * 2 + 1];
    out[idx] = g_y[(size_t)sA * H + h] + g_y[(size_t)sB * H + h];
}

// ---------------- launch ----------------
extern "C" void kernel_launch(void* const* d_in, const int* in_sizes, int n_in,
                              void* d_out, int out_size) {
    const float* x  = (const float*)d_in[0];
    const float* gw = (const float*)d_in[1];
    const float* gb = (const float*)d_in[2];
    const float* w1 = (const float*)d_in[3];
    const float* b1 = (const float*)d_in[4];
    const float* w2 = (const float*)d_in[5];
    const float* b2 = (const float*)d_in[6];
    float* out = (float*)d_out;

    init_kernel<<<1, 32>>>();
    router_kernel<<<T / 8, 256>>>(x, gw, gb);
    scan_kernel<<<1, 32>>>();
    place_kernel<<<T / 256, 256>>>();

    // grid.y = 8 covers worst case (one expert gets all T=1024 tokens)
    dim3 g1(F / BN, 8, E);    // (64, 8, 8)
    gemm1_kernel<<<g1, 256>>>(x, w1, b1);
    dim3 g2(H / BN, 8, E);    // (16, 8, 8)
    gemm2_kernel<<<g2, 256>>>(w2, b2);

    combine_kernel<<<(T * H) / 256, 256>>>(out);
}

// round 5
// speedup vs baseline: 1.9901x; 1.0919x over previous
#include <cuda_runtime.h>
#include <math.h>

// Problem constants
#define T 1024
#define H 1024
#define F 4096
#define E 8
#define NSLOT (2*T)

// GEMM tiling (tensor-core version)
#define BM 128
#define BN 128
#define BK 16
#define AS_STRIDE (BM + 4)   // 132
#define BS_STRIDE (BN + 4)   // 132

// ---------------- device scratch (no allocation allowed) ----------------
__device__ int   g_cnt[E];
__device__ int   g_off[E];
__device__ int   g_fill[E];
__device__ int   g_slot_tok[NSLOT];
__device__ float g_slot_w[NSLOT];
__device__ int   g_tok_slot[NSLOT];
__device__ int   g_tok_e[NSLOT];
__device__ float g_tok_wt[NSLOT];
__device__ float g_h[(size_t)NSLOT * F];   // 32 MB
__device__ float g_y[(size_t)NSLOT * H];   // 8 MB

// ---------------- helpers ----------------
__device__ __forceinline__ unsigned f2tf32(float f) {
    unsigned r;
    asm("cvt.rna.tf32.f32 %0, %1;" : "=r"(r) : "f"(f));
    return r;
}

__device__ __forceinline__ void mma_tf32(float* c, const unsigned* a, const unsigned* b) {
    asm volatile(
        "mma.sync.aligned.m16n8k8.row.col.f32.tf32.tf32.f32 "
        "{%0,%1,%2,%3}, {%4,%5,%6,%7}, {%8,%9}, {%0,%1,%2,%3};\n"
        : "+f"(c[0]), "+f"(c[1]), "+f"(c[2]), "+f"(c[3])
        : "r"(a[0]), "r"(a[1]), "r"(a[2]), "r"(a[3]), "r"(b[0]), "r"(b[1]));
}

// ---------------- tiny setup kernels ----------------
__global__ void init_kernel() {
    int i = threadIdx.x;
    if (i < E) { g_cnt[i] = 0; g_fill[i] = 0; }
}

__global__ void router_kernel(const float* __restrict__ x,
                              const float* __restrict__ gw,
                              const float* __restrict__ gb) {
    int t    = (blockIdx.x * blockDim.x + threadIdx.x) >> 5;
    int lane = threadIdx.x & 31;
    if (t >= T) return;
    const float* xr = x + (size_t)t * H;
    float acc[E];
#pragma unroll
    for (int e = 0; e < E; e++) acc[e] = 0.f;
    for (int h = lane; h < H; h += 32) {
        float xv = xr[h];
#pragma unroll
        for (int e = 0; e < E; e++) acc[e] = fmaf(xv, gw[e * H + h], acc[e]);
    }
#pragma unroll
    for (int e = 0; e < E; e++) {
#pragma unroll
        for (int o = 16; o > 0; o >>= 1)
            acc[e] += __shfl_xor_sync(0xffffffffu, acc[e], o);
    }
    if (lane == 0) {
        float lg[E];
#pragma unroll
        for (int e = 0; e < E; e++) lg[e] = acc[e] + gb[e];
        int e0 = 0; float l0 = lg[0];
#pragma unroll
        for (int e = 1; e < E; e++) if (lg[e] > l0) { l0 = lg[e]; e0 = e; }
        int e1 = -1; float l1 = -3.0e38f;
#pragma unroll
        for (int e = 0; e < E; e++)
            if (e != e0 && lg[e] > l1) { l1 = lg[e]; e1 = e; }
        float w1v = 1.f / (1.f + expf(l0 - l1));
        float w0v = 1.f - w1v;
        g_tok_e [t * 2]     = e0;  g_tok_wt[t * 2]     = w0v;
        g_tok_e [t * 2 + 1] = e1;  g_tok_wt[t * 2 + 1] = w1v;
        atomicAdd(&g_cnt[e0], 1);
        atomicAdd(&g_cnt[e1], 1);
    }
}

__global__ void scan_kernel() {
    if (threadIdx.x == 0) {
        int s = 0;
        for (int e = 0; e < E; e++) { g_off[e] = s; s += g_cnt[e]; }
    }
}

__global__ void place_kernel() {
    int t = blockIdx.x * blockDim.x + threadIdx.x;
    if (t >= T) return;
#pragma unroll
    for (int k = 0; k < 2; k++) {
        int e = g_tok_e[t * 2 + k];
        int local = atomicAdd(&g_fill[e], 1);
        int slot = g_off[e] + local;
        g_slot_tok[slot]      = t;
        g_slot_w[slot]        = g_tok_wt[t * 2 + k];
        g_tok_slot[t * 2 + k] = slot;
    }
}

// ---------------- GEMM1: h = gelu(gather(x) @ w1[e] + b1[e]) ----------------
// 256 threads = 8 warps in 2x4; warp tile 64x32 (4x4 m16n8k8 atoms)
__global__ __launch_bounds__(256) void gemm1_kernel(
    const float* __restrict__ x, const float* __restrict__ w1,
    const float* __restrict__ b1) {
    int e   = blockIdx.z;
    int cnt = g_cnt[e];
    int m0  = blockIdx.y * BM;
    if (m0 >= cnt) return;
    int off = g_off[e];
    int n0  = blockIdx.x * BN;

    __shared__ float As[2][BK][AS_STRIDE];
    __shared__ float Bs[2][BK][BS_STRIDE];
    __shared__ int   stok[BM];

    int tid = threadIdx.x;
    if (tid < BM) {
        int r = m0 + tid;
        stok[tid] = (r < cnt) ? g_slot_tok[off + r] : -1;
    }
    __syncthreads();

    int warp  = tid >> 5;
    int lane  = tid & 31;
    int warpM = warp >> 2;        // 0..1
    int warpN = warp & 3;         // 0..3
    int wm0   = warpM * 64;
    int wn0   = warpN * 32;
    int qid   = lane >> 2;        // 0..7
    int qr    = lane & 3;         // 0..3

    const float* w1e = w1 + (size_t)e * H * F;

    float acc[4][4][4];
#pragma unroll
    for (int mi = 0; mi < 4; mi++)
#pragma unroll
        for (int nj = 0; nj < 4; nj++)
#pragma unroll
            for (int c = 0; c < 4; c++) acc[mi][nj][c] = 0.f;

    float4 ra[2], rb[2];
    // A: 128x16 floats = 512 float4 -> 2/thread. id: row=id>>2, c4=id&3
    int a_row[2], a_c4[2];
#pragma unroll
    for (int i = 0; i < 2; i++) { int id = tid + i * 256; a_row[i] = id >> 2; a_c4[i] = id & 3; }
    // B: 16x128 floats = 512 float4 -> 2/thread. id: row=id>>5, c4=id&31
    int b_row[2], b_c4[2];
#pragma unroll
    for (int i = 0; i < 2; i++) { int id = tid + i * 256; b_row[i] = id >> 5; b_c4[i] = id & 31; }

    // prologue: tile 0
#pragma unroll
    for (int i = 0; i < 2; i++) {
        int tok = stok[a_row[i]];
        ra[i] = (tok >= 0) ? *(const float4*)(x + (size_t)tok * H + a_c4[i] * 4)
                           : make_float4(0.f, 0.f, 0.f, 0.f);
        rb[i] = *(const float4*)(w1e + (size_t)b_row[i] * F + n0 + b_c4[i] * 4);
    }
#pragma unroll
    for (int i = 0; i < 2; i++) {
        int k = a_c4[i] * 4, r = a_row[i];
        As[0][k + 0][r] = __uint_as_float(f2tf32(ra[i].x));
        As[0][k + 1][r] = __uint_as_float(f2tf32(ra[i].y));
        As[0][k + 2][r] = __uint_as_float(f2tf32(ra[i].z));
        As[0][k + 3][r] = __uint_as_float(f2tf32(ra[i].w));
        int c = b_c4[i] * 4;
        Bs[0][b_row[i]][c + 0] = __uint_as_float(f2tf32(rb[i].x));
        Bs[0][b_row[i]][c + 1] = __uint_as_float(f2tf32(rb[i].y));
        Bs[0][b_row[i]][c + 2] = __uint_as_float(f2tf32(rb[i].z));
        Bs[0][b_row[i]][c + 3] = __uint_as_float(f2tf32(rb[i].w));
    }
    __syncthreads();

    const int NK = H / BK;   // 64
    for (int it = 0; it < NK; ++it) {
        int buf = it & 1;
        if (it + 1 < NK) {
            int k0 = (it + 1) * BK;
#pragma unroll
            for (int i = 0; i < 2; i++) {
                int tok = stok[a_row[i]];
                ra[i] = (tok >= 0) ? *(const float4*)(x + (size_t)tok * H + k0 + a_c4[i] * 4)
                                   : make_float4(0.f, 0.f, 0.f, 0.f);
                rb[i] = *(const float4*)(w1e + (size_t)(k0 + b_row[i]) * F + n0 + b_c4[i] * 4);
            }
        }
#pragma unroll
        for (int ks = 0; ks < 2; ++ks) {
            unsigned af[4][4], bf[4][2];
            int kb = ks * 8 + qr;
#pragma unroll
            for (int mi = 0; mi < 4; mi++) {
                int r = wm0 + mi * 16 + qid;
                af[mi][0] = __float_as_uint(As[buf][kb][r]);
                af[mi][1] = __float_as_uint(As[buf][kb][r + 8]);
                af[mi][2] = __float_as_uint(As[buf][kb + 4][r]);
                af[mi][3] = __float_as_uint(As[buf][kb + 4][r + 8]);
            }
#pragma unroll
            for (int nj = 0; nj < 4; nj++) {
                int c = wn0 + nj * 8 + qid;
                bf[nj][0] = __float_as_uint(Bs[buf][kb][c]);
                bf[nj][1] = __float_as_uint(Bs[buf][kb + 4][c]);
            }
#pragma unroll
            for (int mi = 0; mi < 4; mi++)
#pragma unroll
                for (int nj = 0; nj < 4; nj++)
                    mma_tf32(acc[mi][nj], af[mi], bf[nj]);
        }
        __syncthreads();
        if (it + 1 < NK) {
            int nb = buf ^ 1;
#pragma unroll
            for (int i = 0; i < 2; i++) {
                int k = a_c4[i] * 4, r = a_row[i];
                As[nb][k + 0][r] = __uint_as_float(f2tf32(ra[i].x));
                As[nb][k + 1][r] = __uint_as_float(f2tf32(ra[i].y));
                As[nb][k + 2][r] = __uint_as_float(f2tf32(ra[i].z));
                As[nb][k + 3][r] = __uint_as_float(f2tf32(ra[i].w));
                int c = b_c4[i] * 4;
                Bs[nb][b_row[i]][c + 0] = __uint_as_float(f2tf32(rb[i].x));
                Bs[nb][b_row[i]][c + 1] = __uint_as_float(f2tf32(rb[i].y));
                Bs[nb][b_row[i]][c + 2] = __uint_as_float(f2tf32(rb[i].z));
                Bs[nb][b_row[i]][c + 3] = __uint_as_float(f2tf32(rb[i].w));
            }
            __syncthreads();
        }
    }

    // epilogue: bias + exact gelu, scatter to g_h
    const float* b1e = b1 + (size_t)e * F;
#pragma unroll
    for (int mi = 0; mi < 4; mi++) {
#pragma unroll
        for (int half = 0; half < 2; half++) {
            int r = m0 + wm0 + mi * 16 + qid + half * 8;
            if (r >= cnt) continue;
            float* hrow = g_h + (size_t)(off + r) * F;
#pragma unroll
            for (int nj = 0; nj < 4; nj++) {
                int col = n0 + wn0 + nj * 8 + 2 * qr;
                float v0 = acc[mi][nj][half * 2 + 0] + b1e[col];
                float v1 = acc[mi][nj][half * 2 + 1] + b1e[col + 1];
                hrow[col]     = 0.5f * v0 * (1.f + erff(v0 * 0.70710678118654752440f));
                hrow[col + 1] = 0.5f * v1 * (1.f + erff(v1 * 0.70710678118654752440f));
            }
        }
    }
}

// ---------------- GEMM2: y = weight * (h @ w2[e] + b2[e]) ----------------
__global__ __launch_bounds__(256) void gemm2_kernel(
    const float* __restrict__ w2, const float* __restrict__ b2) {
    int e   = blockIdx.z;
    int cnt = g_cnt[e];
    int m0  = blockIdx.y * BM;
    if (m0 >= cnt) return;
    int off = g_off[e];
    int n0  = blockIdx.x * BN;

    __shared__ float As[2][BK][AS_STRIDE];
    __shared__ float Bs[2][BK][BS_STRIDE];

    int tid = threadIdx.x;
    int warp  = tid >> 5;
    int lane  = tid & 31;
    int warpM = warp >> 2;
    int warpN = warp & 3;
    int wm0   = warpM * 64;
    int wn0   = warpN * 32;
    int qid   = lane >> 2;
    int qr    = lane & 3;

    const float* w2e = w2 + (size_t)e * F * H;

    float acc[4][4][4];
#pragma unroll
    for (int mi = 0; mi < 4; mi++)
#pragma unroll
        for (int nj = 0; nj < 4; nj++)
#pragma unroll
            for (int c = 0; c < 4; c++) acc[mi][nj][c] = 0.f;

    float4 ra[2], rb[2];
    int a_row[2], a_c4[2];
    bool a_ok[2];
    const float* a_base[2];
#pragma unroll
    for (int i = 0; i < 2; i++) {
        int id = tid + i * 256;
        a_row[i] = id >> 2; a_c4[i] = id & 3;
        int r = m0 + a_row[i];
        a_ok[i] = (r < cnt);
        a_base[i] = g_h + (size_t)(off + (a_ok[i] ? r : 0)) * F;
    }
    int b_row[2], b_c4[2];
#pragma unroll
    for (int i = 0; i < 2; i++) { int id = tid + i * 256; b_row[i] = id >> 5; b_c4[i] = id & 31; }

#pragma unroll
    for (int i = 0; i < 2; i++) {
        ra[i] = a_ok[i] ? *(const float4*)(a_base[i] + a_c4[i] * 4)
                        : make_float4(0.f, 0.f, 0.f, 0.f);
        rb[i] = *(const float4*)(w2e + (size_t)b_row[i] * H + n0 + b_c4[i] * 4);
    }
#pragma unroll
    for (int i = 0; i < 2; i++) {
        int k = a_c4[i] * 4, r = a_row[i];
        As[0][k + 0][r] = __uint_as_float(f2tf32(ra[i].x));
        As[0][k + 1][r] = __uint_as_float(f2tf32(ra[i].y));
        As[0][k + 2][r] = __uint_as_float(f2tf32(ra[i].z));
        As[0][k + 3][r] = __uint_as_float(f2tf32(ra[i].w));
        int c = b_c4[i] * 4;
        Bs[0][b_row[i]][c + 0] = __uint_as_float(f2tf32(rb[i].x));
        Bs[0][b_row[i]][c + 1] = __uint_as_float(f2tf32(rb[i].y));
        Bs[0][b_row[i]][c + 2] = __uint_as_float(f2tf32(rb[i].z));
        Bs[0][b_row[i]][c + 3] = __uint_as_float(f2tf32(rb[i].w));
    }
    __syncthreads();

    const int NK = F / BK;   // 256
    for (int it = 0; it < NK; ++it) {
        int buf = it & 1;
        if (it + 1 < NK) {
            int k0 = (it + 1) * BK;
#pragma unroll
            for (int i = 0; i < 2; i++) {
                ra[i] = a_ok[i] ? *(const float4*)(a_base[i] + k0 + a_c4[i] * 4)
                                : make_float4(0.f, 0.f, 0.f, 0.f);
                rb[i] = *(const float4*)(w2e + (size_t)(k0 + b_row[i]) * H + n0 + b_c4[i] * 4);
            }
        }
#pragma unroll
        for (int ks = 0; ks < 2; ++ks) {
            unsigned af[4][4], bf[4][2];
            int kb = ks * 8 + qr;
#pragma unroll
            for (int mi = 0; mi < 4; mi++) {
                int r = wm0 + mi * 16 + qid;
                af[mi][0] = __float_as_uint(As[buf][kb][r]);
                af[mi][1] = __float_as_uint(As[buf][kb][r + 8]);
                af[mi][2] = __float_as_uint(As[buf][kb + 4][r]);
                af[mi][3] = __float_as_uint(As[buf][kb + 4][r + 8]);
            }
#pragma unroll
            for (int nj = 0; nj < 4; nj++) {
                int c = wn0 + nj * 8 + qid;
                bf[nj][0] = __float_as_uint(Bs[buf][kb][c]);
                bf[nj][1] = __float_as_uint(Bs[buf][kb + 4][c]);
            }
#pragma unroll
            for (int mi = 0; mi < 4; mi++)
#pragma unroll
                for (int nj = 0; nj < 4; nj++)
                    mma_tf32(acc[mi][nj], af[mi], bf[nj]);
        }
        __syncthreads();
        if (it + 1 < NK) {
            int nb = buf ^ 1;
#pragma unroll
            for (int i = 0; i < 2; i++) {
                int k = a_c4[i] * 4, r = a_row[i];
                As[nb][k + 0][r] = __uint_as_float(f2tf32(ra[i].x));
                As[nb][k + 1][r] = __uint_as_float(f2tf32(ra[i].y));
                As[nb][k + 2][r] = __uint_as_float(f2tf32(ra[i].z));
                As[nb][k + 3][r] = __uint_as_float(f2tf32(ra[i].w));
                int c = b_c4[i] * 4;
                Bs[nb][b_row[i]][c + 0] = __uint_as_float(f2tf32(rb[i].x));
                Bs[nb][b_row[i]][c + 1] = __uint_as_float(f2tf32(rb[i].y));
                Bs[nb][b_row[i]][c + 2] = __uint_as_float(f2tf32(rb[i].z));
                Bs[nb][b_row[i]][c + 3] = __uint_as_float(f2tf32(rb[i].w));
            }
            __syncthreads();
        }
    }

    const float* b2e = b2 + (size_t)e * H;
#pragma unroll
    for (int mi = 0; mi < 4; mi++) {
#pragma unroll
        for (int half = 0; half < 2; half++) {
            int r = m0 + wm0 + mi * 16 + qid + half * 8;
            if (r >= cnt) continue;
            int slot = off + r;
            float wgt = g_slot_w[slot];
            float* yrow = g_y + (size_t)slot * H;
#pragma unroll
            for (int nj = 0; nj < 4; nj++) {
                int col = n0 + wn0 + nj * 8 + 2 * qr;
                yrow[col]     = wgt * (acc[mi][nj][half * 2 + 0] + b2e[col]);
                yrow[col + 1] = wgt * (acc[mi][nj][half * 2 + 1] + b2e[col + 1]);
            }
        }
    }
}

// ---------------- combine ----------------
__global__ void combine_kernel(float* __restrict__ out) {
    int idx = blockIdx.x * blockDim.x + threadIdx.x;
    int t = idx >> 10;
    int h = idx & (H - 1);
    int sA = g_tok_slot[t * 2];
    int sB = g_tok_slot[t * 2 + 1];
    out[idx] = g_y[(size_t)sA * H + h] + g_y[(size_t)sB * H + h];
}

// ---------------- launch ----------------
extern "C" void kernel_launch(void* const* d_in, const int* in_sizes, int n_in,
                              void* d_out, int out_size) {
    const float* x  = (const float*)d_in[0];
    const float* gw = (const float*)d_in[1];
    const float* gb = (const float*)d_in[2];
    const float* w1 = (const float*)d_in[3];
    const float* b1 = (const float*)d_in[4];
    const float* w2 = (const float*)d_in[5];
    const float* b2 = (const float*)d_in[6];
    float* out = (float*)d_out;

    init_kernel<<<1, 32>>>();
    router_kernel<<<T / 8, 256>>>(x, gw, gb);
    scan_kernel<<<1, 32>>>();
    place_kernel<<<T / 256, 256>>>();

    dim3 g1(F / BN, 8, E);    // (32, 8, 8); blocks beyond count exit early
    gemm1_kernel<<<g1, 256>>>(x, w1, b1);
    dim3 g2(H / BN, 8, E);    // (8, 8, 8)
    gemm2_kernel<<<g2, 256>>>(w2, b2);

    combine_kernel<<<(T * H) / 256, 256>>>(out);
}

// round 7
// speedup vs baseline: 3.4268x; 1.7220x over previous
#include <cuda_runtime.h>
#include <cuda_fp16.h>
#include <math.h>
#include <stdint.h>

// Problem constants
#define T 1024
#define H 1024
#define F 4096
#define E 8
#define NSLOT (2*T)
#define PAD_ROWS 256

// GEMM tiling (fp16 mma.sync m16n8k16)
#define BM 128
#define BN 128
#define BK 32
#define A_WSTRIDE 20   // words per A row: 16 data (32 halves) + 4 pad -> conflict-free frags, 16B-aligned STS.128
#define B_HSTRIDE 34   // halves per B row: 32 data + 2 pad (17-word stride)

// ---------------- device scratch ----------------
__device__ int    g_cnt[E];
__device__ int    g_off[E];
__device__ int    g_fill[E];
__device__ int    g_slot_tok[NSLOT];
__device__ float  g_slot_w[NSLOT];
__device__ int    g_tok_slot[NSLOT];
__device__ int    g_tok_e[NSLOT];
__device__ float  g_tok_wt[NSLOT];
__device__ __half g_xg[(size_t)(NSLOT + PAD_ROWS) * H];  // gathered tokens, fp16
__device__ __half g_h[(size_t)(NSLOT + PAD_ROWS) * F];   // gelu(x@w1+b1), fp16
__device__ float  g_yp[(size_t)2 * NSLOT * H];           // split-K partials

// ---------------- helpers ----------------
__device__ __forceinline__ void mma_f16(float* c, const uint32_t* a, const uint32_t* b) {
    asm volatile(
        "mma.sync.aligned.m16n8k16.row.col.f32.f16.f16.f32 "
        "{%0,%1,%2,%3}, {%4,%5,%6,%7}, {%8,%9}, {%0,%1,%2,%3};\n"
        : "+f"(c[0]), "+f"(c[1]), "+f"(c[2]), "+f"(c[3])
        : "r"(a[0]), "r"(a[1]), "r"(a[2]), "r"(a[3]), "r"(b[0]), "r"(b[1]));
}

// ---------------- setup kernels ----------------
__global__ void init_kernel() {
    int i = threadIdx.x;
    if (i < E) { g_cnt[i] = 0; g_fill[i] = 0; }
}

__global__ void router_kernel(const float* __restrict__ x,
                              const float* __restrict__ gw,
                              const float* __restrict__ gb) {
    int t    = (blockIdx.x * blockDim.x + threadIdx.x) >> 5;
    int lane = threadIdx.x & 31;
    if (t >= T) return;
    const float* xr = x + (size_t)t * H;
    float acc[E];
#pragma unroll
    for (int e = 0; e < E; e++) acc[e] = 0.f;
    for (int h = lane; h < H; h += 32) {
        float xv = xr[h];
#pragma unroll
        for (int e = 0; e < E; e++) acc[e] = fmaf(xv, gw[e * H + h], acc[e]);
    }
#pragma unroll
    for (int e = 0; e < E; e++) {
#pragma unroll
        for (int o = 16; o > 0; o >>= 1)
            acc[e] += __shfl_xor_sync(0xffffffffu, acc[e], o);
    }
    if (lane == 0) {
        float lg[E];
#pragma unroll
        for (int e = 0; e < E; e++) lg[e] = acc[e] + gb[e];
        int e0 = 0; float l0 = lg[0];
#pragma unroll
        for (int e = 1; e < E; e++) if (lg[e] > l0) { l0 = lg[e]; e0 = e; }
        int e1 = -1; float l1 = -3.0e38f;
#pragma unroll
        for (int e = 0; e < E; e++)
            if (e != e0 && lg[e] > l1) { l1 = lg[e]; e1 = e; }
        float w1v = 1.f / (1.f + expf(l0 - l1));
        float w0v = 1.f - w1v;
        g_tok_e [t * 2]     = e0;  g_tok_wt[t * 2]     = w0v;
        g_tok_e [t * 2 + 1] = e1;  g_tok_wt[t * 2 + 1] = w1v;
        atomicAdd(&g_cnt[e0], 1);
        atomicAdd(&g_cnt[e1], 1);
    }
}

__global__ void scan_kernel() {
    if (threadIdx.x == 0) {
        int s = 0;
        for (int e = 0; e < E; e++) { g_off[e] = s; s += g_cnt[e]; }
    }
}

__global__ void place_kernel() {
    int t = blockIdx.x * blockDim.x + threadIdx.x;
    if (t >= T) return;
#pragma unroll
    for (int k = 0; k < 2; k++) {
        int e = g_tok_e[t * 2 + k];
        int local = atomicAdd(&g_fill[e], 1);
        int slot = g_off[e] + local;
        g_slot_tok[slot]      = t;
        g_slot_w[slot]        = g_tok_wt[t * 2 + k];
        g_tok_slot[t * 2 + k] = slot;
    }
}

// pack tokens contiguously per slot, fp32 -> fp16 (rn); zero the pad region
__global__ void gather_kernel(const float* __restrict__ x) {
    int idx  = blockIdx.x * blockDim.x + threadIdx.x;  // over (NSLOT+PAD)*128 8-half chunks
    int slot = idx >> 7;
    int c    = idx & 127;
    uint4 o;
    if (slot < NSLOT) {
        int tok = g_slot_tok[slot];
        const float4* src = (const float4*)(x + (size_t)tok * H + c * 8);
        float4 v0 = src[0], v1 = src[1];
        __half2 h0 = __floats2half2_rn(v0.x, v0.y);
        __half2 h1 = __floats2half2_rn(v0.z, v0.w);
        __half2 h2 = __floats2half2_rn(v1.x, v1.y);
        __half2 h3 = __floats2half2_rn(v1.z, v1.w);
        o.x = *(uint32_t*)&h0; o.y = *(uint32_t*)&h1;
        o.z = *(uint32_t*)&h2; o.w = *(uint32_t*)&h3;
    } else {
        o.x = o.y = o.z = o.w = 0u;
    }
    ((uint4*)g_xg)[(size_t)slot * 128 + c] = o;
}

// ---------------- GEMM1: g_h = gelu(g_xg @ w1[e] + b1[e]) ----------------
// 256 threads = 8 warps in 2x4; warp tile 64x32 (4x4 m16n8k16 atoms)
__global__ __launch_bounds__(256, 2) void gemm1_kernel(
    const float* __restrict__ w1, const float* __restrict__ b1) {
    int e   = blockIdx.z;
    int cnt = g_cnt[e];
    int m0  = blockIdx.y * BM;
    if (m0 >= cnt) return;
    int off = g_off[e];
    int n0  = blockIdx.x * BN;

    __shared__ uint32_t AsW[2][BM * A_WSTRIDE];   // 20 KB
    __shared__ __half   BsH[2][BN * B_HSTRIDE];   // 17 KB

    int tid  = threadIdx.x;
    int warp = tid >> 5;
    int lane = tid & 31;
    int wm0  = (warp >> 2) * 64;
    int wn0  = (warp & 3) * 32;
    int qid  = lane >> 2;
    int qr   = lane & 3;

    const float* w1e = w1 + (size_t)e * H * F;
    const __half* ag = g_xg + (size_t)(off + m0) * H;

    float acc[4][4][4];
#pragma unroll
    for (int mi = 0; mi < 4; mi++)
#pragma unroll
        for (int nj = 0; nj < 4; nj++)
#pragma unroll
            for (int c = 0; c < 4; c++) acc[mi][nj][c] = 0.f;

    // A: 512 uint4 (8 halves each) -> 2/thread: row=id>>2, k8=id&3
    int a_row[2], a_k8[2];
#pragma unroll
    for (int i = 0; i < 2; i++) { int id = tid + i * 256; a_row[i] = id >> 2; a_k8[i] = id & 3; }
    // B: 32x128 floats = 1024 float4 -> 4/thread: kk=id>>5, n4=id&31
    int b_kk[4], b_n4[4];
#pragma unroll
    for (int i = 0; i < 4; i++) { int id = tid + i * 256; b_kk[i] = id >> 5; b_n4[i] = id & 31; }

    uint4  ra[2];
    float4 rb[4];

    // prologue: tile 0
#pragma unroll
    for (int i = 0; i < 2; i++)
        ra[i] = ((const uint4*)(ag + (size_t)a_row[i] * H))[a_k8[i]];
#pragma unroll
    for (int i = 0; i < 4; i++)
        rb[i] = *(const float4*)(w1e + (size_t)b_kk[i] * F + n0 + b_n4[i] * 4);
#pragma unroll
    for (int i = 0; i < 2; i++)
        *(uint4*)&AsW[0][a_row[i] * A_WSTRIDE + a_k8[i] * 4] = ra[i];
#pragma unroll
    for (int i = 0; i < 4; i++) {
        int hb = b_n4[i] * 4 * B_HSTRIDE + b_kk[i];
        BsH[0][hb + 0 * B_HSTRIDE] = __float2half_rn(rb[i].x);
        BsH[0][hb + 1 * B_HSTRIDE] = __float2half_rn(rb[i].y);
        BsH[0][hb + 2 * B_HSTRIDE] = __float2half_rn(rb[i].z);
        BsH[0][hb + 3 * B_HSTRIDE] = __float2half_rn(rb[i].w);
    }
    __syncthreads();

    const int NK = H / BK;   // 32
    for (int it = 0; it < NK; ++it) {
        int buf = it & 1;
        if (it + 1 < NK) {
            int k0 = (it + 1) * BK;
#pragma unroll
            for (int i = 0; i < 2; i++)
                ra[i] = ((const uint4*)(ag + (size_t)a_row[i] * H + k0))[a_k8[i]];
#pragma unroll
            for (int i = 0; i < 4; i++)
                rb[i] = *(const float4*)(w1e + (size_t)(k0 + b_kk[i]) * F + n0 + b_n4[i] * 4);
        }
#pragma unroll
        for (int ks = 0; ks < 2; ++ks) {
            uint32_t af[4][4], bf[4][2];
            int kp = ks * 8 + qr;
#pragma unroll
            for (int mi = 0; mi < 4; mi++) {
                int r = wm0 + mi * 16 + qid;
                af[mi][0] = AsW[buf][r * A_WSTRIDE + kp];
                af[mi][1] = AsW[buf][(r + 8) * A_WSTRIDE + kp];
                af[mi][2] = AsW[buf][r * A_WSTRIDE + kp + 4];
                af[mi][3] = AsW[buf][(r + 8) * A_WSTRIDE + kp + 4];
            }
#pragma unroll
            for (int nj = 0; nj < 4; nj++) {
                int n = wn0 + nj * 8 + qid;
                bf[nj][0] = *(const uint32_t*)&BsH[buf][n * B_HSTRIDE + kp * 2];
                bf[nj][1] = *(const uint32_t*)&BsH[buf][n * B_HSTRIDE + (kp + 4) * 2];
            }
#pragma unroll
            for (int mi = 0; mi < 4; mi++)
#pragma unroll
                for (int nj = 0; nj < 4; nj++)
                    mma_f16(acc[mi][nj], af[mi], bf[nj]);
        }
        __syncthreads();
        if (it + 1 < NK) {
            int nb = buf ^ 1;
#pragma unroll
            for (int i = 0; i < 2; i++)
                *(uint4*)&AsW[nb][a_row[i] * A_WSTRIDE + a_k8[i] * 4] = ra[i];
#pragma unroll
            for (int i = 0; i < 4; i++) {
                int hb = b_n4[i] * 4 * B_HSTRIDE + b_kk[i];
                BsH[nb][hb + 0 * B_HSTRIDE] = __float2half_rn(rb[i].x);
                BsH[nb][hb + 1 * B_HSTRIDE] = __float2half_rn(rb[i].y);
                BsH[nb][hb + 2 * B_HSTRIDE] = __float2half_rn(rb[i].z);
                BsH[nb][hb + 3 * B_HSTRIDE] = __float2half_rn(rb[i].w);
            }
            __syncthreads();
        }
    }

    // epilogue: bias + exact gelu -> fp16 g_h
    const float* b1e = b1 + (size_t)e * F;
#pragma unroll
    for (int mi = 0; mi < 4; mi++) {
#pragma unroll
        for (int half_ = 0; half_ < 2; half_++) {
            int r = m0 + wm0 + mi * 16 + qid + half_ * 8;
            if (r >= cnt) continue;
            __half* hrow = g_h + (size_t)(off + r) * F;
#pragma unroll
            for (int nj = 0; nj < 4; nj++) {
                int col = n0 + wn0 + nj * 8 + 2 * qr;
                float v0 = acc[mi][nj][half_ * 2 + 0] + b1e[col];
                float v1 = acc[mi][nj][half_ * 2 + 1] + b1e[col + 1];
                float o0 = 0.5f * v0 * (1.f + erff(v0 * 0.70710678118654752440f));
                float o1 = 0.5f * v1 * (1.f + erff(v1 * 0.70710678118654752440f));
                *(__half2*)(hrow + col) = __floats2half2_rn(o0, o1);
            }
        }
    }
}

// ---------------- GEMM2 (split-K=2): g_yp[kh] = w*(g_h @ w2[e][Kslice] + b2?) ----------------
__global__ __launch_bounds__(256, 2) void gemm2_kernel(
    const float* __restrict__ w2, const float* __restrict__ b2) {
    int e   = blockIdx.z >> 1;
    int kh  = blockIdx.z & 1;
    int cnt = g_cnt[e];
    int m0  = blockIdx.y * BM;
    if (m0 >= cnt) return;
    int off = g_off[e];
    int n0  = blockIdx.x * BN;
    int kbase = kh * (F / 2);   // 2048

    __shared__ uint32_t AsW[2][BM * A_WSTRIDE];
    __shared__ __half   BsH[2][BN * B_HSTRIDE];

    int tid  = threadIdx.x;
    int warp = tid >> 5;
    int lane = tid & 31;
    int wm0  = (warp >> 2) * 64;
    int wn0  = (warp & 3) * 32;
    int qid  = lane >> 2;
    int qr   = lane & 3;

    const float* w2e = w2 + (size_t)e * F * H;
    const __half* ag = g_h + (size_t)(off + m0) * F + kbase;

    float acc[4][4][4];
#pragma unroll
    for (int mi = 0; mi < 4; mi++)
#pragma unroll
        for (int nj = 0; nj < 4; nj++)
#pragma unroll
            for (int c = 0; c < 4; c++) acc[mi][nj][c] = 0.f;

    int a_row[2], a_k8[2];
#pragma unroll
    for (int i = 0; i < 2; i++) { int id = tid + i * 256; a_row[i] = id >> 2; a_k8[i] = id & 3; }
    int b_kk[4], b_n4[4];
#pragma unroll
    for (int i = 0; i < 4; i++) { int id = tid + i * 256; b_kk[i] = id >> 5; b_n4[i] = id & 31; }

    uint4  ra[2];
    float4 rb[4];

#pragma unroll
    for (int i = 0; i < 2; i++)
        ra[i] = ((const uint4*)(ag + (size_t)a_row[i] * F))[a_k8[i]];
#pragma unroll
    for (int i = 0; i < 4; i++)
        rb[i] = *(const float4*)(w2e + (size_t)(kbase + b_kk[i]) * H + n0 + b_n4[i] * 4);
#pragma unroll
    for (int i = 0; i < 2; i++)
        *(uint4*)&AsW[0][a_row[i] * A_WSTRIDE + a_k8[i] * 4] = ra[i];
#pragma unroll
    for (int i = 0; i < 4; i++) {
        int hb = b_n4[i] * 4 * B_HSTRIDE + b_kk[i];
        BsH[0][hb + 0 * B_HSTRIDE] = __float2half_rn(rb[i].x);
        BsH[0][hb + 1 * B_HSTRIDE] = __float2half_rn(rb[i].y);
        BsH[0][hb + 2 * B_HSTRIDE] = __float2half_rn(rb[i].z);
        BsH[0][hb + 3 * B_HSTRIDE] = __float2half_rn(rb[i].w);
    }
    __syncthreads();

    const int NK = (F / 2) / BK;   // 64
    for (int it = 0; it < NK; ++it) {
        int buf = it & 1;
        if (it + 1 < NK) {
            int k0 = (it + 1) * BK;
#pragma unroll
            for (int i = 0; i < 2; i++)
                ra[i] = ((const uint4*)(ag + (size_t)a_row[i] * F + k0))[a_k8[i]];
#pragma unroll
            for (int i = 0; i < 4; i++)
                rb[i] = *(const float4*)(w2e + (size_t)(kbase + k0 + b_kk[i]) * H + n0 + b_n4[i] * 4);
        }
#pragma unroll
        for (int ks = 0; ks < 2; ++ks) {
            uint32_t af[4][4], bf[4][2];
            int kp = ks * 8 + qr;
#pragma unroll
            for (int mi = 0; mi < 4; mi++) {
                int r = wm0 + mi * 16 + qid;
                af[mi][0] = AsW[buf][r * A_WSTRIDE + kp];
                af[mi][1] = AsW[buf][(r + 8) * A_WSTRIDE + kp];
                af[mi][2] = AsW[buf][r * A_WSTRIDE + kp + 4];
                af[mi][3] = AsW[buf][(r + 8) * A_WSTRIDE + kp + 4];
            }
#pragma unroll
            for (int nj = 0; nj < 4; nj++) {
                int n = wn0 + nj * 8 + qid;
                bf[nj][0] = *(const uint32_t*)&BsH[buf][n * B_HSTRIDE + kp * 2];
                bf[nj][1] = *(const uint32_t*)&BsH[buf][n * B_HSTRIDE + (kp + 4) * 2];
            }
#pragma unroll
            for (int mi = 0; mi < 4; mi++)
#pragma unroll
                for (int nj = 0; nj < 4; nj++)
                    mma_f16(acc[mi][nj], af[mi], bf[nj]);
        }
        __syncthreads();
        if (it + 1 < NK) {
            int nb = buf ^ 1;
#pragma unroll
            for (int i = 0; i < 2; i++)
                *(uint4*)&AsW[nb][a_row[i] * A_WSTRIDE + a_k8[i] * 4] = ra[i];
#pragma unroll
            for (int i = 0; i < 4; i++) {
                int hb = b_n4[i] * 4 * B_HSTRIDE + b_kk[i];
                BsH[nb][hb + 0 * B_HSTRIDE] = __float2half_rn(rb[i].x);
                BsH[nb][hb + 1 * B_HSTRIDE] = __float2half_rn(rb[i].y);
                BsH[nb][hb + 2 * B_HSTRIDE] = __float2half_rn(rb[i].z);
                BsH[nb][hb + 3 * B_HSTRIDE] = __float2half_rn(rb[i].w);
            }
            __syncthreads();
        }
    }

    const float* b2e = b2 + (size_t)e * H;
    float* ybase = g_yp + (size_t)kh * NSLOT * H;
#pragma unroll
    for (int mi = 0; mi < 4; mi++) {
#pragma unroll
        for (int half_ = 0; half_ < 2; half_++) {
            int r = m0 + wm0 + mi * 16 + qid + half_ * 8;
            if (r >= cnt) continue;
            int slot = off + r;
            float wgt = g_slot_w[slot];
            float* yrow = ybase + (size_t)slot * H;
#pragma unroll
            for (int nj = 0; nj < 4; nj++) {
                int col = n0 + wn0 + nj * 8 + 2 * qr;
                float bb0 = (kh == 0) ? b2e[col]     : 0.f;
                float bb1 = (kh == 0) ? b2e[col + 1] : 0.f;
                yrow[col]     = wgt * (acc[mi][nj][half_ * 2 + 0] + bb0);
                yrow[col + 1] = wgt * (acc[mi][nj][half_ * 2 + 1] + bb1);
            }
        }
    }
}

// ---------------- combine: out[t] = sum over 2 experts x 2 K-halves ----------------
__global__ void combine_kernel(float* __restrict__ out) {
    int idx = blockIdx.x * blockDim.x + threadIdx.x;
    int t = idx >> 10;
    int h = idx & (H - 1);
    size_t oA = (size_t)g_tok_slot[t * 2] * H + h;
    size_t oB = (size_t)g_tok_slot[t * 2 + 1] * H + h;
    const size_t NH = (size_t)NSLOT * H;
    out[idx] = (g_yp[oA] + g_yp[NH + oA]) + (g_yp[oB] + g_yp[NH + oB]);
}

// ---------------- launch ----------------
extern "C" void kernel_launch(void* const* d_in, const int* in_sizes, int n_in,
                              void* d_out, int out_size) {
    const float* x  = (const float*)d_in[0];
    const float* gw = (const float*)d_in[1];
    const float* gb = (const float*)d_in[2];
    const float* w1 = (const float*)d_in[3];
    const float* b1 = (const float*)d_in[4];
    const float* w2 = (const float*)d_in[5];
    const float* b2 = (const float*)d_in[6];
    float* out = (float*)d_out;

    init_kernel<<<1, 32>>>();
    router_kernel<<<T / 8, 256>>>(x, gw, gb);
    scan_kernel<<<1, 32>>>();
    place_kernel<<<T / 256, 256>>>();
    gather_kernel<<<((NSLOT + PAD_ROWS) * 128) / 256, 256>>>(x);

    dim3 g1(F / BN, 8, E);        // (32, 8, 8); blocks beyond count exit early
    gemm1_kernel<<<g1, 256>>>(w1, b1);
    dim3 g2(H / BN, 8, E * 2);    // (8, 8, 16): split-K=2
    gemm2_kernel<<<g2, 256>>>(w2, b2);

    combine_kernel<<<(T * H) / 256, 256>>>(out);
}

// round 8
// speedup vs baseline: 4.7236x; 1.3784x over previous
#include <cuda_runtime.h>
#include <cuda_fp16.h>
#include <math.h>
#include <stdint.h>

// Problem constants
#define T 1024
#define H 1024
#define F 4096
#define E 8
#define NSLOT (2*T)
#define PAD_ROWS 256

// GEMM tiling (fp16 mma.sync m16n8k16 + ldmatrix + cp.async)
#define BM 128
#define BN 128
#define BK 32
#define A_STAGE_BYTES 8192   // 128 rows * 64 B (32 halves)
#define B_STAGE_BYTES 8192   // 32 rows * 256 B (128 halves)

// ---------------- device scratch ----------------
__device__ int    g_cnt[E];
__device__ int    g_off[E];
__device__ int    g_fill[E];
__device__ int    g_slot_tok[NSLOT];
__device__ float  g_slot_w[NSLOT];
__device__ int    g_tok_slot[NSLOT];
__device__ int    g_tok_e[NSLOT];
__device__ float  g_tok_wt[NSLOT];
__device__ __half g_xg[(size_t)(NSLOT + PAD_ROWS) * H];  // gathered tokens, fp16
__device__ __half g_h[(size_t)(NSLOT + PAD_ROWS) * F];   // gelu(x@w1+b1), fp16
__device__ float  g_yp[(size_t)2 * NSLOT * H];           // split-K partials

// ---------------- PTX helpers ----------------
__device__ __forceinline__ uint32_t smem_u32(const void* p) {
    uint32_t a;
    asm("{ .reg .u64 t; cvta.to.shared.u64 t, %1; cvt.u32.u64 %0, t; }" : "=r"(a) : "l"(p));
    return a;
}
__device__ __forceinline__ void mma_f16(float* c, const uint32_t* a, const uint32_t* b) {
    asm volatile(
        "mma.sync.aligned.m16n8k16.row.col.f32.f16.f16.f32 "
        "{%0,%1,%2,%3}, {%4,%5,%6,%7}, {%8,%9}, {%0,%1,%2,%3};\n"
        : "+f"(c[0]), "+f"(c[1]), "+f"(c[2]), "+f"(c[3])
        : "r"(a[0]), "r"(a[1]), "r"(a[2]), "r"(a[3]), "r"(b[0]), "r"(b[1]));
}
__device__ __forceinline__ void ldmx4(uint32_t* r, uint32_t addr) {
    asm volatile("ldmatrix.sync.aligned.m8n8.x4.shared.b16 {%0,%1,%2,%3}, [%4];"
                 : "=r"(r[0]), "=r"(r[1]), "=r"(r[2]), "=r"(r[3]) : "r"(addr));
}
__device__ __forceinline__ void ldmx4t(uint32_t* r, uint32_t addr) {
    asm volatile("ldmatrix.sync.aligned.m8n8.x4.trans.shared.b16 {%0,%1,%2,%3}, [%4];"
                 : "=r"(r[0]), "=r"(r[1]), "=r"(r[2]), "=r"(r[3]) : "r"(addr));
}
#define CP_ASYNC16(dst, src) \
    asm volatile("cp.async.ca.shared.global [%0], [%1], 16;" :: "r"(dst), "l"(src))
#define CP_COMMIT() asm volatile("cp.async.commit_group;" ::: "memory")
#define CP_WAIT0()  asm volatile("cp.async.wait_group 0;" ::: "memory")

// ---------------- setup kernels ----------------
__global__ void init_kernel() {
    int i = threadIdx.x;
    if (i < E) { g_cnt[i] = 0; g_fill[i] = 0; }
}

__global__ void router_kernel(const float* __restrict__ x,
                              const float* __restrict__ gw,
                              const float* __restrict__ gb) {
    int t    = (blockIdx.x * blockDim.x + threadIdx.x) >> 5;
    int lane = threadIdx.x & 31;
    if (t >= T) return;
    const float* xr = x + (size_t)t * H;
    float acc[E];
#pragma unroll
    for (int e = 0; e < E; e++) acc[e] = 0.f;
    for (int h = lane; h < H; h += 32) {
        float xv = xr[h];
#pragma unroll
        for (int e = 0; e < E; e++) acc[e] = fmaf(xv, gw[e * H + h], acc[e]);
    }
#pragma unroll
    for (int e = 0; e < E; e++) {
#pragma unroll
        for (int o = 16; o > 0; o >>= 1)
            acc[e] += __shfl_xor_sync(0xffffffffu, acc[e], o);
    }
    if (lane == 0) {
        float lg[E];
#pragma unroll
        for (int e = 0; e < E; e++) lg[e] = acc[e] + gb[e];
        int e0 = 0; float l0 = lg[0];
#pragma unroll
        for (int e = 1; e < E; e++) if (lg[e] > l0) { l0 = lg[e]; e0 = e; }
        int e1 = -1; float l1 = -3.0e38f;
#pragma unroll
        for (int e = 0; e < E; e++)
            if (e != e0 && lg[e] > l1) { l1 = lg[e]; e1 = e; }
        float w1v = 1.f / (1.f + expf(l0 - l1));
        float w0v = 1.f - w1v;
        g_tok_e [t * 2]     = e0;  g_tok_wt[t * 2]     = w0v;
        g_tok_e [t * 2 + 1] = e1;  g_tok_wt[t * 2 + 1] = w1v;
        atomicAdd(&g_cnt[e0], 1);
        atomicAdd(&g_cnt[e1], 1);
    }
}

__global__ void scan_kernel() {
    if (threadIdx.x == 0) {
        int s = 0;
        for (int e = 0; e < E; e++) { g_off[e] = s; s += g_cnt[e]; }
    }
}

__global__ void place_kernel() {
    int t = blockIdx.x * blockDim.x + threadIdx.x;
    if (t >= T) return;
#pragma unroll
    for (int k = 0; k < 2; k++) {
        int e = g_tok_e[t * 2 + k];
        int local = atomicAdd(&g_fill[e], 1);
        int slot = g_off[e] + local;
        g_slot_tok[slot]      = t;
        g_slot_w[slot]        = g_tok_wt[t * 2 + k];
        g_tok_slot[t * 2 + k] = slot;
    }
}

// pack tokens contiguously per slot, fp32 -> fp16 (rn); zero the pad region
__global__ void gather_kernel(const float* __restrict__ x) {
    int idx  = blockIdx.x * blockDim.x + threadIdx.x;
    int slot = idx >> 7;
    int c    = idx & 127;
    uint4 o;
    if (slot < NSLOT) {
        int tok = g_slot_tok[slot];
        const float4* src = (const float4*)(x + (size_t)tok * H + c * 8);
        float4 v0 = src[0], v1 = src[1];
        __half2 h0 = __floats2half2_rn(v0.x, v0.y);
        __half2 h1 = __floats2half2_rn(v0.z, v0.w);
        __half2 h2 = __floats2half2_rn(v1.x, v1.y);
        __half2 h3 = __floats2half2_rn(v1.z, v1.w);
        o.x = *(uint32_t*)&h0; o.y = *(uint32_t*)&h1;
        o.z = *(uint32_t*)&h2; o.w = *(uint32_t*)&h3;
    } else {
        o.x = o.y = o.z = o.w = 0u;
    }
    ((uint4*)g_xg)[(size_t)slot * 128 + c] = o;
}

// Pack 8 floats -> uint4 of 8 halves
__device__ __forceinline__ uint4 pack8h(float4 a, float4 b) {
    __half2 h0 = __floats2half2_rn(a.x, a.y);
    __half2 h1 = __floats2half2_rn(a.z, a.w);
    __half2 h2 = __floats2half2_rn(b.x, b.y);
    __half2 h3 = __floats2half2_rn(b.z, b.w);
    uint4 o;
    o.x = *(uint32_t*)&h0; o.y = *(uint32_t*)&h1;
    o.z = *(uint32_t*)&h2; o.w = *(uint32_t*)&h3;
    return o;
}

// ================= shared GEMM core (macro-free, templated by flags) =================
// A smem: [row][32 halves], 64 B pitch, seg swizzle: seg ^= (row>>1)&3
// B smem: [k][128 halves], 256 B pitch, seg swizzle: seg ^= k&7

struct GemmCtx {
    uint32_t sA, sB;        // smem bases
    int tid, warp, lane, wm0, wn0, qid, qr;
    int l15, l16, aswz, bswz;
    int a_row[2]; uint32_t a_dst[2];   // cp.async A
    int b_k[2], b_n[2];                // B tile ids
};

__device__ __forceinline__ void gemm_init(GemmCtx& c, uint32_t sA, uint32_t sB) {
    c.sA = sA; c.sB = sB;
    c.tid = threadIdx.x; c.warp = c.tid >> 5; c.lane = c.tid & 31;
    c.wm0 = (c.warp >> 2) * 64; c.wn0 = (c.warp & 3) * 32;
    c.qid = c.lane >> 2; c.qr = c.lane & 3;
    c.l15 = c.lane & 15; c.l16 = c.lane >> 4;
    c.aswz = (c.l15 >> 1) & 3;
    c.bswz = c.l15 & 7;
#pragma unroll
    for (int i = 0; i < 2; i++) {
        int id = c.tid + i * 256;
        c.a_row[i] = id >> 2;
        int k8 = id & 3;
        c.a_dst[i] = (uint32_t)(c.a_row[i] * 64 + ((k8 ^ ((c.a_row[i] >> 1) & 3)) << 4));
        c.b_k[i] = id >> 4; c.b_n[i] = id & 15;
    }
}

__device__ __forceinline__ void gemm_compute(const GemmCtx& c, int buf, float acc[4][4][4]) {
    uint32_t abase = c.sA + buf * A_STAGE_BYTES + c.wm0 * 64 + (uint32_t)c.l15 * 64;
    uint32_t bbase = c.sB + buf * B_STAGE_BYTES + (uint32_t)c.l15 * 256;
    int wn8 = c.wn0 >> 3;
#pragma unroll
    for (int ks = 0; ks < 2; ++ks) {
        uint32_t af[4][4], bf[4][2];
#pragma unroll
        for (int mi = 0; mi < 4; mi++)
            ldmx4(af[mi], abase + mi * 1024 + ((((ks * 2 + c.l16) ^ c.aswz)) << 4));
#pragma unroll
        for (int g = 0; g < 2; g++) {
            uint32_t r[4];
            ldmx4t(r, bbase + ks * 4096 + (((wn8 + 2 * g + c.l16) ^ c.bswz) << 4));
            bf[2 * g][0] = r[0]; bf[2 * g][1] = r[1];
            bf[2 * g + 1][0] = r[2]; bf[2 * g + 1][1] = r[3];
        }
#pragma unroll
        for (int mi = 0; mi < 4; mi++)
#pragma unroll
            for (int nj = 0; nj < 4; nj++)
                mma_f16(acc[mi][nj], af[mi], bf[nj]);
    }
}

// issue A cp.async for a tile into stage buf
__device__ __forceinline__ void gemm_loadA(const GemmCtx& c, int buf,
                                           const __half* ag, size_t pitch, int k0) {
#pragma unroll
    for (int i = 0; i < 2; i++) {
        int id = c.tid + i * 256;
        int k8 = id & 3;
        CP_ASYNC16(c.sA + buf * A_STAGE_BYTES + c.a_dst[i],
                   ag + (size_t)c.a_row[i] * pitch + k0 + k8 * 8);
    }
    CP_COMMIT();
}

__device__ __forceinline__ void gemm_fetchB(const GemmCtx& c, const float* wB,
                                            size_t pitch, int k0, int n0, float4 rb[4]) {
#pragma unroll
    for (int i = 0; i < 2; i++) {
        const float* p = wB + (size_t)(k0 + c.b_k[i]) * pitch + n0 + c.b_n[i] * 8;
        rb[2 * i]     = *(const float4*)p;
        rb[2 * i + 1] = *(const float4*)(p + 4);
    }
}

__device__ __forceinline__ void gemm_storeB(const GemmCtx& c, int buf, const float4 rb[4]) {
#pragma unroll
    for (int i = 0; i < 2; i++) {
        uint4 h = pack8h(rb[2 * i], rb[2 * i + 1]);
        uint32_t dst = c.sB + buf * B_STAGE_BYTES +
                       (uint32_t)(c.b_k[i] * 256 + ((c.b_n[i] ^ (c.b_k[i] & 7)) << 4));
        asm volatile("st.shared.v4.b32 [%0], {%1,%2,%3,%4};"
                     :: "r"(dst), "r"(h.x), "r"(h.y), "r"(h.z), "r"(h.w) : "memory");
    }
}

// ---------------- GEMM1: g_h = gelu(g_xg @ w1[e] + b1[e]) ----------------
__global__ __launch_bounds__(256, 2) void gemm1_kernel(
    const float* __restrict__ w1, const float* __restrict__ b1) {
    int e   = blockIdx.z;
    int cnt = g_cnt[e];
    int m0  = blockIdx.y * BM;
    if (m0 >= cnt) return;
    int off = g_off[e];
    int n0  = blockIdx.x * BN;

    __shared__ __align__(16) char As[2 * A_STAGE_BYTES];
    __shared__ __align__(16) char Bs[2 * B_STAGE_BYTES];

    GemmCtx c;
    gemm_init(c, smem_u32(As), smem_u32(Bs));

    const float* w1e = w1 + (size_t)e * H * F;
    const __half* ag = g_xg + (size_t)(off + m0) * H;

    float acc[4][4][4];
#pragma unroll
    for (int mi = 0; mi < 4; mi++)
#pragma unroll
        for (int nj = 0; nj < 4; nj++)
#pragma unroll
            for (int q = 0; q < 4; q++) acc[mi][nj][q] = 0.f;

    float4 rb[4];
    // prologue: stage 0
    gemm_loadA(c, 0, ag, H, 0);
    gemm_fetchB(c, w1e, F, 0, n0, rb);
    gemm_storeB(c, 0, rb);
    CP_WAIT0();
    __syncthreads();

    const int NK = H / BK;   // 32
    for (int it = 0; it < NK; ++it) {
        int buf = it & 1, nb = buf ^ 1;
        if (it + 1 < NK) {
            int k0 = (it + 1) * BK;
            gemm_loadA(c, nb, ag, H, k0);
            gemm_fetchB(c, w1e, F, k0, n0, rb);
        }
        gemm_compute(c, buf, acc);
        __syncthreads();
        if (it + 1 < NK) {
            gemm_storeB(c, nb, rb);
            CP_WAIT0();
            __syncthreads();
        }
    }

    // epilogue: bias + exact gelu -> fp16 g_h
    const float* b1e = b1 + (size_t)e * F;
#pragma unroll
    for (int mi = 0; mi < 4; mi++) {
#pragma unroll
        for (int hh = 0; hh < 2; hh++) {
            int r = m0 + c.wm0 + mi * 16 + c.qid + hh * 8;
            if (r >= cnt) continue;
            __half* hrow = g_h + (size_t)(off + r) * F;
#pragma unroll
            for (int nj = 0; nj < 4; nj++) {
                int col = n0 + c.wn0 + nj * 8 + 2 * c.qr;
                float v0 = acc[mi][nj][hh * 2 + 0] + b1e[col];
                float v1 = acc[mi][nj][hh * 2 + 1] + b1e[col + 1];
                float o0 = 0.5f * v0 * (1.f + erff(v0 * 0.70710678118654752440f));
                float o1 = 0.5f * v1 * (1.f + erff(v1 * 0.70710678118654752440f));
                *(__half2*)(hrow + col) = __floats2half2_rn(o0, o1);
            }
        }
    }
}

// ---------------- GEMM2 (split-K=2): g_yp[kh] = w*(g_h @ w2[e][Kslice] + b2?) ----------------
__global__ __launch_bounds__(256, 2) void gemm2_kernel(
    const float* __restrict__ w2, const float* __restrict__ b2) {
    int e   = blockIdx.z >> 1;
    int kh  = blockIdx.z & 1;
    int cnt = g_cnt[e];
    int m0  = blockIdx.y * BM;
    if (m0 >= cnt) return;
    int off = g_off[e];
    int n0  = blockIdx.x * BN;
    int kbase = kh * (F / 2);

    __shared__ __align__(16) char As[2 * A_STAGE_BYTES];
    __shared__ __align__(16) char Bs[2 * B_STAGE_BYTES];

    GemmCtx c;
    gemm_init(c, smem_u32(As), smem_u32(Bs));

    const float* w2e = w2 + (size_t)e * F * H;
    const __half* ag = g_h + (size_t)(off + m0) * F + kbase;

    float acc[4][4][4];
#pragma unroll
    for (int mi = 0; mi < 4; mi++)
#pragma unroll
        for (int nj = 0; nj < 4; nj++)
#pragma unroll
            for (int q = 0; q < 4; q++) acc[mi][nj][q] = 0.f;

    float4 rb[4];
    gemm_loadA(c, 0, ag, F, 0);
    gemm_fetchB(c, w2e, H, kbase, n0, rb);
    gemm_storeB(c, 0, rb);
    CP_WAIT0();
    __syncthreads();

    const int NK = (F / 2) / BK;   // 64
    for (int it = 0; it < NK; ++it) {
        int buf = it & 1, nb = buf ^ 1;
        if (it + 1 < NK) {
            int k0 = (it + 1) * BK;
            gemm_loadA(c, nb, ag, F, k0);
            gemm_fetchB(c, w2e, H, kbase + k0, n0, rb);
        }
        gemm_compute(c, buf, acc);
        __syncthreads();
        if (it + 1 < NK) {
            gemm_storeB(c, nb, rb);
            CP_WAIT0();
            __syncthreads();
        }
    }

    const float* b2e = b2 + (size_t)e * H;
    float* ybase = g_yp + (size_t)kh * NSLOT * H;
#pragma unroll
    for (int mi = 0; mi < 4; mi++) {
#pragma unroll
        for (int hh = 0; hh < 2; hh++) {
            int r = m0 + c.wm0 + mi * 16 + c.qid + hh * 8;
            if (r >= cnt) continue;
            int slot = off + r;
            float wgt = g_slot_w[slot];
            float* yrow = ybase + (size_t)slot * H;
#pragma unroll
            for (int nj = 0; nj < 4; nj++) {
                int col = n0 + c.wn0 + nj * 8 + 2 * c.qr;
                float bb0 = (kh == 0) ? b2e[col]     : 0.f;
                float bb1 = (kh == 0) ? b2e[col + 1] : 0.f;
                yrow[col]     = wgt * (acc[mi][nj][hh * 2 + 0] + bb0);
                yrow[col + 1] = wgt * (acc[mi][nj][hh * 2 + 1] + bb1);
            }
        }
    }
}

// ---------------- combine ----------------
__global__ void combine_kernel(float* __restrict__ out) {
    int idx = blockIdx.x * blockDim.x + threadIdx.x;
    int t = idx >> 10;
    int h = idx & (H - 1);
    size_t oA = (size_t)g_tok_slot[t * 2] * H + h;
    size_t oB = (size_t)g_tok_slot[t * 2 + 1] * H + h;
    const size_t NH = (size_t)NSLOT * H;
    out[idx] = (g_yp[oA] + g_yp[NH + oA]) + (g_yp[oB] + g_yp[NH + oB]);
}

// ---------------- launch ----------------
extern "C" void kernel_launch(void* const* d_in, const int* in_sizes, int n_in,
                              void* d_out, int out_size) {
    const float* x  = (const float*)d_in[0];
    const float* gw = (const float*)d_in[1];
    const float* gb = (const float*)d_in[2];
    const float* w1 = (const float*)d_in[3];
    const float* b1 = (const float*)d_in[4];
    const float* w2 = (const float*)d_in[5];
    const float* b2 = (const float*)d_in[6];
    float* out = (float*)d_out;

    init_kernel<<<1, 32>>>();
    router_kernel<<<T / 8, 256>>>(x, gw, gb);
    scan_kernel<<<1, 32>>>();
    place_kernel<<<T / 256, 256>>>();
    gather_kernel<<<((NSLOT + PAD_ROWS) * 128) / 256, 256>>>(x);

    dim3 g1(F / BN, 8, E);        // (32, 8, 8); blocks beyond count exit early
    gemm1_kernel<<<g1, 256>>>(w1, b1);
    dim3 g2(H / BN, 8, E * 2);    // (8, 8, 16): split-K=2
    gemm2_kernel<<<g2, 256>>>(w2, b2);

    combine_kernel<<<(T * H) / 256, 256>>>(out);
}

// round 9
// speedup vs baseline: 5.0073x; 1.0601x over previous
#include <cuda_runtime.h>
#include <cuda_fp16.h>
#include <math.h>
#include <stdint.h>

// Problem constants
#define T 1024
#define H 1024
#define F 4096
#define E 8
#define NSLOT (2*T)
#define PAD_ROWS 256

// GEMM tiling (fp16 mma.sync m16n8k16 + ldmatrix + multi-stage cp.async)
#define BM 128
#define BN 128
#define BK 32
#define A_STAGES 4
#define B_STAGES 2
#define A_STAGE_BYTES 8192   // 128 rows * 64 B (32 halves)
#define B_STAGE_BYTES 8192   // 32 rows * 256 B (128 halves)

// ---------------- device scratch ----------------
__device__ int    g_cnt[E];
__device__ int    g_off[E];
__device__ int    g_fill[E];
__device__ int    g_slot_tok[NSLOT];
__device__ float  g_slot_w[NSLOT];
__device__ int    g_tok_slot[NSLOT];
__device__ int    g_tok_e[NSLOT];
__device__ float  g_tok_wt[NSLOT];
__device__ __half g_xg[(size_t)(NSLOT + PAD_ROWS) * H];  // gathered tokens, fp16
__device__ __half g_h[(size_t)(NSLOT + PAD_ROWS) * F];   // gelu(x@w1+b1), fp16
__device__ float  g_yp[(size_t)2 * NSLOT * H];           // split-K partials

// ---------------- PTX helpers ----------------
__device__ __forceinline__ uint32_t smem_u32(const void* p) {
    uint32_t a;
    asm("{ .reg .u64 t; cvta.to.shared.u64 t, %1; cvt.u32.u64 %0, t; }" : "=r"(a) : "l"(p));
    return a;
}
__device__ __forceinline__ void mma_f16(float* c, const uint32_t* a, const uint32_t* b) {
    asm volatile(
        "mma.sync.aligned.m16n8k16.row.col.f32.f16.f16.f32 "
        "{%0,%1,%2,%3}, {%4,%5,%6,%7}, {%8,%9}, {%0,%1,%2,%3};\n"
        : "+f"(c[0]), "+f"(c[1]), "+f"(c[2]), "+f"(c[3])
        : "r"(a[0]), "r"(a[1]), "r"(a[2]), "r"(a[3]), "r"(b[0]), "r"(b[1]));
}
__device__ __forceinline__ void ldmx4(uint32_t* r, uint32_t addr) {
    asm volatile("ldmatrix.sync.aligned.m8n8.x4.shared.b16 {%0,%1,%2,%3}, [%4];"
                 : "=r"(r[0]), "=r"(r[1]), "=r"(r[2]), "=r"(r[3]) : "r"(addr));
}
__device__ __forceinline__ void ldmx4t(uint32_t* r, uint32_t addr) {
    asm volatile("ldmatrix.sync.aligned.m8n8.x4.trans.shared.b16 {%0,%1,%2,%3}, [%4];"
                 : "=r"(r[0]), "=r"(r[1]), "=r"(r[2]), "=r"(r[3]) : "r"(addr));
}
#define CP_ASYNC16(dst, src) \
    asm volatile("cp.async.ca.shared.global [%0], [%1], 16;" :: "r"(dst), "l"(src))
#define CP_COMMIT() asm volatile("cp.async.commit_group;" ::: "memory")
#define CP_WAIT2()  asm volatile("cp.async.wait_group 2;" ::: "memory")

// ---------------- setup kernels ----------------
__global__ void init_kernel() {
    int i = threadIdx.x;
    if (i < E) { g_cnt[i] = 0; g_fill[i] = 0; }
}

__global__ void router_kernel(const float* __restrict__ x,
                              const float* __restrict__ gw,
                              const float* __restrict__ gb) {
    int t    = (blockIdx.x * blockDim.x + threadIdx.x) >> 5;
    int lane = threadIdx.x & 31;
    if (t >= T) return;
    const float* xr = x + (size_t)t * H;
    float acc[E];
#pragma unroll
    for (int e = 0; e < E; e++) acc[e] = 0.f;
    for (int h = lane; h < H; h += 32) {
        float xv = xr[h];
#pragma unroll
        for (int e = 0; e < E; e++) acc[e] = fmaf(xv, gw[e * H + h], acc[e]);
    }
#pragma unroll
    for (int e = 0; e < E; e++) {
#pragma unroll
        for (int o = 16; o > 0; o >>= 1)
            acc[e] += __shfl_xor_sync(0xffffffffu, acc[e], o);
    }
    if (lane == 0) {
        float lg[E];
#pragma unroll
        for (int e = 0; e < E; e++) lg[e] = acc[e] + gb[e];
        int e0 = 0; float l0 = lg[0];
#pragma unroll
        for (int e = 1; e < E; e++) if (lg[e] > l0) { l0 = lg[e]; e0 = e; }
        int e1 = -1; float l1 = -3.0e38f;
#pragma unroll
        for (int e = 0; e < E; e++)
            if (e != e0 && lg[e] > l1) { l1 = lg[e]; e1 = e; }
        float w1v = 1.f / (1.f + expf(l0 - l1));
        float w0v = 1.f - w1v;
        g_tok_e [t * 2]     = e0;  g_tok_wt[t * 2]     = w0v;
        g_tok_e [t * 2 + 1] = e1;  g_tok_wt[t * 2 + 1] = w1v;
        atomicAdd(&g_cnt[e0], 1);
        atomicAdd(&g_cnt[e1], 1);
    }
}

__global__ void scan_kernel() {
    if (threadIdx.x == 0) {
        int s = 0;
        for (int e = 0; e < E; e++) { g_off[e] = s; s += g_cnt[e]; }
    }
}

__global__ void place_kernel() {
    int t = blockIdx.x * blockDim.x + threadIdx.x;
    if (t >= T) return;
#pragma unroll
    for (int k = 0; k < 2; k++) {
        int e = g_tok_e[t * 2 + k];
        int local = atomicAdd(&g_fill[e], 1);
        int slot = g_off[e] + local;
        g_slot_tok[slot]      = t;
        g_slot_w[slot]        = g_tok_wt[t * 2 + k];
        g_tok_slot[t * 2 + k] = slot;
    }
}

// pack tokens contiguously per slot, fp32 -> fp16 (rn); zero the pad region
__global__ void gather_kernel(const float* __restrict__ x) {
    int idx  = blockIdx.x * blockDim.x + threadIdx.x;
    int slot = idx >> 7;
    int c    = idx & 127;
    uint4 o;
    if (slot < NSLOT) {
        int tok = g_slot_tok[slot];
        const float4* src = (const float4*)(x + (size_t)tok * H + c * 8);
        float4 v0 = src[0], v1 = src[1];
        __half2 h0 = __floats2half2_rn(v0.x, v0.y);
        __half2 h1 = __floats2half2_rn(v0.z, v0.w);
        __half2 h2 = __floats2half2_rn(v1.x, v1.y);
        __half2 h3 = __floats2half2_rn(v1.z, v1.w);
        o.x = *(uint32_t*)&h0; o.y = *(uint32_t*)&h1;
        o.z = *(uint32_t*)&h2; o.w = *(uint32_t*)&h3;
    } else {
        o.x = o.y = o.z = o.w = 0u;
    }
    ((uint4*)g_xg)[(size_t)slot * 128 + c] = o;
}

// Pack 8 floats -> uint4 of 8 halves
__device__ __forceinline__ uint4 pack8h(float4 a, float4 b) {
    __half2 h0 = __floats2half2_rn(a.x, a.y);
    __half2 h1 = __floats2half2_rn(a.z, a.w);
    __half2 h2 = __floats2half2_rn(b.x, b.y);
    __half2 h3 = __floats2half2_rn(b.z, b.w);
    uint4 o;
    o.x = *(uint32_t*)&h0; o.y = *(uint32_t*)&h1;
    o.z = *(uint32_t*)&h2; o.w = *(uint32_t*)&h3;
    return o;
}

// ================= shared GEMM core =================
// A smem: 4 stages, [row][32 halves], 64 B pitch, seg swizzle: seg ^= (row>>1)&3
// B smem: 2 stages, [k][128 halves], 256 B pitch, seg swizzle: seg ^= k&7

struct GemmCtx {
    uint32_t sA, sB;
    int tid, warp, lane, wm0, wn0, qid, qr;
    int l15, l16, aswz, bswz;
    int a_row[2]; uint32_t a_dst[2];
    int b_k[2], b_n[2];
};

__device__ __forceinline__ void gemm_init(GemmCtx& c, uint32_t sA, uint32_t sB) {
    c.sA = sA; c.sB = sB;
    c.tid = threadIdx.x; c.warp = c.tid >> 5; c.lane = c.tid & 31;
    c.wm0 = (c.warp >> 2) * 64; c.wn0 = (c.warp & 3) * 32;
    c.qid = c.lane >> 2; c.qr = c.lane & 3;
    c.l15 = c.lane & 15; c.l16 = c.lane >> 4;
    c.aswz = (c.l15 >> 1) & 3;
    c.bswz = c.l15 & 7;
#pragma unroll
    for (int i = 0; i < 2; i++) {
        int id = c.tid + i * 256;
        c.a_row[i] = id >> 2;
        int k8 = id & 3;
        c.a_dst[i] = (uint32_t)(c.a_row[i] * 64 + ((k8 ^ ((c.a_row[i] >> 1) & 3)) << 4));
        c.b_k[i] = id >> 4; c.b_n[i] = id & 15;
    }
}

__device__ __forceinline__ void gemm_compute(const GemmCtx& c, int ab, int bb,
                                             float acc[4][4][4]) {
    uint32_t abase = c.sA + ab * A_STAGE_BYTES + c.wm0 * 64 + (uint32_t)c.l15 * 64;
    uint32_t bbase = c.sB + bb * B_STAGE_BYTES + (uint32_t)c.l15 * 256;
    int wn8 = c.wn0 >> 3;
#pragma unroll
    for (int ks = 0; ks < 2; ++ks) {
        uint32_t af[4][4], bf[4][2];
#pragma unroll
        for (int mi = 0; mi < 4; mi++)
            ldmx4(af[mi], abase + mi * 1024 + ((((ks * 2 + c.l16) ^ c.aswz)) << 4));
#pragma unroll
        for (int g = 0; g < 2; g++) {
            uint32_t r[4];
            ldmx4t(r, bbase + ks * 4096 + (((wn8 + 2 * g + c.l16) ^ c.bswz) << 4));
            bf[2 * g][0] = r[0]; bf[2 * g][1] = r[1];
            bf[2 * g + 1][0] = r[2]; bf[2 * g + 1][1] = r[3];
        }
#pragma unroll
        for (int mi = 0; mi < 4; mi++)
#pragma unroll
            for (int nj = 0; nj < 4; nj++)
                mma_f16(acc[mi][nj], af[mi], bf[nj]);
    }
}

// issue A cp.async for a tile into stage buf (commits one group)
__device__ __forceinline__ void gemm_loadA(const GemmCtx& c, int buf,
                                           const __half* ag, size_t pitch, int k0) {
#pragma unroll
    for (int i = 0; i < 2; i++) {
        int id = c.tid + i * 256;
        int k8 = id & 3;
        CP_ASYNC16(c.sA + buf * A_STAGE_BYTES + c.a_dst[i],
                   ag + (size_t)c.a_row[i] * pitch + k0 + k8 * 8);
    }
    CP_COMMIT();
}

__device__ __forceinline__ void gemm_fetchB(const GemmCtx& c, const float* wB,
                                            size_t pitch, int k0, int n0, float4 rb[4]) {
#pragma unroll
    for (int i = 0; i < 2; i++) {
        const float* p = wB + (size_t)(k0 + c.b_k[i]) * pitch + n0 + c.b_n[i] * 8;
        rb[2 * i]     = *(const float4*)p;
        rb[2 * i + 1] = *(const float4*)(p + 4);
    }
}

__device__ __forceinline__ void gemm_storeB(const GemmCtx& c, int buf, const float4 rb[4]) {
#pragma unroll
    for (int i = 0; i < 2; i++) {
        uint4 h = pack8h(rb[2 * i], rb[2 * i + 1]);
        uint32_t dst = c.sB + buf * B_STAGE_BYTES +
                       (uint32_t)(c.b_k[i] * 256 + ((c.b_n[i] ^ (c.b_k[i] & 7)) << 4));
        asm volatile("st.shared.v4.b32 [%0], {%1,%2,%3,%4};"
                     :: "r"(dst), "r"(h.x), "r"(h.y), "r"(h.z), "r"(h.w) : "memory");
    }
}

// Pipelined mainloop shared by both GEMMs.
// A: 4-stage cp.async (3 tiles in flight, wait_group 2).
// B: fp32 LDG one iteration ahead into regs, cvt+STS at iteration end.
// Exactly one __syncthreads per iteration.
__device__ __forceinline__ void gemm_mainloop(const GemmCtx& c,
                                              const __half* ag, size_t apitch,
                                              const float* wB, size_t bpitch,
                                              int kb0, int n0, int NK,
                                              float acc[4][4][4]) {
    float4 rb[4];
    // prologue: A stages 0..2, B stage 0
    gemm_loadA(c, 0, ag, apitch, 0);
    gemm_loadA(c, 1, ag, apitch, BK);
    gemm_loadA(c, 2, ag, apitch, 2 * BK);
    gemm_fetchB(c, wB, bpitch, kb0, n0, rb);
    gemm_storeB(c, 0, rb);

    for (int it = 0; it < NK; ++it) {
        CP_WAIT2();          // A stage it%4 complete (3 groups in flight)
        __syncthreads();     // B store visible; buffers safe to reuse
        if (it + 1 < NK) gemm_fetchB(c, wB, bpitch, kb0 + (it + 1) * BK, n0, rb);
        if (it + 3 < NK) gemm_loadA(c, (it + 3) & 3, ag, apitch, (it + 3) * BK);
        else             CP_COMMIT();   // keep group count in step
        gemm_compute(c, it & 3, it & 1, acc);
        if (it + 1 < NK) gemm_storeB(c, (it + 1) & 1, rb);
    }
}

// ---------------- GEMM1: g_h = gelu(g_xg @ w1[e] + b1[e]) ----------------
__global__ __launch_bounds__(256, 2) void gemm1_kernel(
    const float* __restrict__ w1, const float* __restrict__ b1) {
    int e   = blockIdx.z;
    int cnt = g_cnt[e];
    int m0  = blockIdx.y * BM;
    if (m0 >= cnt) return;
    int off = g_off[e];
    int n0  = blockIdx.x * BN;

    __shared__ __align__(16) char As[A_STAGES * A_STAGE_BYTES];
    __shared__ __align__(16) char Bs[B_STAGES * B_STAGE_BYTES];

    GemmCtx c;
    gemm_init(c, smem_u32(As), smem_u32(Bs));

    const float* w1e = w1 + (size_t)e * H * F;
    const __half* ag = g_xg + (size_t)(off + m0) * H;

    float acc[4][4][4];
#pragma unroll
    for (int mi = 0; mi < 4; mi++)
#pragma unroll
        for (int nj = 0; nj < 4; nj++)
#pragma unroll
            for (int q = 0; q < 4; q++) acc[mi][nj][q] = 0.f;

    gemm_mainloop(c, ag, H, w1e, F, 0, n0, H / BK, acc);

    // epilogue: bias + exact gelu -> fp16 g_h
    const float* b1e = b1 + (size_t)e * F;
#pragma unroll
    for (int mi = 0; mi < 4; mi++) {
#pragma unroll
        for (int hh = 0; hh < 2; hh++) {
            int r = m0 + c.wm0 + mi * 16 + c.qid + hh * 8;
            if (r >= cnt) continue;
            __half* hrow = g_h + (size_t)(off + r) * F;
#pragma unroll
            for (int nj = 0; nj < 4; nj++) {
                int col = n0 + c.wn0 + nj * 8 + 2 * c.qr;
                float v0 = acc[mi][nj][hh * 2 + 0] + b1e[col];
                float v1 = acc[mi][nj][hh * 2 + 1] + b1e[col + 1];
                float o0 = 0.5f * v0 * (1.f + erff(v0 * 0.70710678118654752440f));
                float o1 = 0.5f * v1 * (1.f + erff(v1 * 0.70710678118654752440f));
                *(__half2*)(hrow + col) = __floats2half2_rn(o0, o1);
            }
        }
    }
}

// ---------------- GEMM2 (split-K=2): g_yp[kh] = w*(g_h @ w2[e][Kslice] + b2?) ----------------
__global__ __launch_bounds__(256, 2) void gemm2_kernel(
    const float* __restrict__ w2, const float* __restrict__ b2) {
    int e   = blockIdx.z >> 1;
    int kh  = blockIdx.z & 1;
    int cnt = g_cnt[e];
    int m0  = blockIdx.y * BM;
    if (m0 >= cnt) return;
    int off = g_off[e];
    int n0  = blockIdx.x * BN;
    int kbase = kh * (F / 2);

    __shared__ __align__(16) char As[A_STAGES * A_STAGE_BYTES];
    __shared__ __align__(16) char Bs[B_STAGES * B_STAGE_BYTES];

    GemmCtx c;
    gemm_init(c, smem_u32(As), smem_u32(Bs));

    const float* w2e = w2 + (size_t)e * F * H;
    const __half* ag = g_h + (size_t)(off + m0) * F + kbase;

    float acc[4][4][4];
#pragma unroll
    for (int mi = 0; mi < 4; mi++)
#pragma unroll
        for (int nj = 0; nj < 4; nj++)
#pragma unroll
            for (int q = 0; q < 4; q++) acc[mi][nj][q] = 0.f;

    gemm_mainloop(c, ag, F, w2e, H, kbase, n0, (F / 2) / BK, acc);

    const float* b2e = b2 + (size_t)e * H;
    float* ybase = g_yp + (size_t)kh * NSLOT * H;
#pragma unroll
    for (int mi = 0; mi < 4; mi++) {
#pragma unroll
        for (int hh = 0; hh < 2; hh++) {
            int r = m0 + c.wm0 + mi * 16 + c.qid + hh * 8;
            if (r >= cnt) continue;
            int slot = off + r;
            float wgt = g_slot_w[slot];
            float* yrow = ybase + (size_t)slot * H;
#pragma unroll
            for (int nj = 0; nj < 4; nj++) {
                int col = n0 + c.wn0 + nj * 8 + 2 * c.qr;
                float bb0 = (kh == 0) ? b2e[col]     : 0.f;
                float bb1 = (kh == 0) ? b2e[col + 1] : 0.f;
                yrow[col]     = wgt * (acc[mi][nj][hh * 2 + 0] + bb0);
                yrow[col + 1] = wgt * (acc[mi][nj][hh * 2 + 1] + bb1);
            }
        }
    }
}

// ---------------- combine ----------------
__global__ void combine_kernel(float* __restrict__ out) {
    int idx = blockIdx.x * blockDim.x + threadIdx.x;
    int t = idx >> 10;
    int h = idx & (H - 1);
    size_t oA = (size_t)g_tok_slot[t * 2] * H + h;
    size_t oB = (size_t)g_tok_slot[t * 2 + 1] * H + h;
    const size_t NH = (size_t)NSLOT * H;
    out[idx] = (g_yp[oA] + g_yp[NH + oA]) + (g_yp[oB] + g_yp[NH + oB]);
}

// ---------------- launch ----------------
extern "C" void kernel_launch(void* const* d_in, const int* in_sizes, int n_in,
                              void* d_out, int out_size) {
    const float* x  = (const float*)d_in[0];
    const float* gw = (const float*)d_in[1];
    const float* gb = (const float*)d_in[2];
    const float* w1 = (const float*)d_in[3];
    const float* b1 = (const float*)d_in[4];
    const float* w2 = (const float*)d_in[5];
    const float* b2 = (const float*)d_in[6];
    float* out = (float*)d_out;

    init_kernel<<<1, 32>>>();
    router_kernel<<<T / 8, 256>>>(x, gw, gb);
    scan_kernel<<<1, 32>>>();
    place_kernel<<<T / 256, 256>>>();
    gather_kernel<<<((NSLOT + PAD_ROWS) * 128) / 256, 256>>>(x);

    dim3 g1(F / BN, 8, E);        // (32, 8, 8); blocks beyond count exit early
    gemm1_kernel<<<g1, 256>>>(w1, b1);
    dim3 g2(H / BN, 8, E * 2);    // (8, 8, 16): split-K=2
    gemm2_kernel<<<g2, 256>>>(w2, b2);

    combine_kernel<<<(T * H) / 256, 256>>>(out);
}